// round 1
// baseline (speedup 1.0000x reference)
#include <cuda_runtime.h>
#include <math.h>

// Problem constants
#define TSEQ 2048
#define DIMC 2048
#define NH   16
#define NKV  4
#define HD   128
#define QKVN 3072      // (16 + 2*4) * 128
#define KOFF 2048      // column offset of K inside qkv
#define VOFF 2560      // column offset of V inside qkv

// Scratch (device globals: allocation-free per harness rules)
__device__ float g_qkv[TSEQ * QKVN];                 // 25 MB
__device__ float g_scores[(size_t)NH * TSEQ * TSEQ]; // 256 MB
__device__ float g_attn[TSEQ * DIMC];                // 17 MB

#define BM 128
#define BN 128
#define BK 8

// ---------------------------------------------------------------------------
// Core 128x128x8 double-buffered fp32 tile GEMM, 256 threads, 8x8 microtile.
// NN variant: C[M,N] += A[M,K] @ B[K,N]   (A row-major lda, B row-major ldb)
// ---------------------------------------------------------------------------
__device__ __forceinline__ void gemm_nn_body(
    const float* __restrict__ A, int lda,
    const float* __restrict__ B, int ldb,
    float* __restrict__ C, int ldc,
    int K, float alpha)
{
    __shared__ float As[2][BK][BM];
    __shared__ float Bs[2][BK][BN];

    const int tid     = threadIdx.x;
    const int rowBase = (tid >> 4) * 8;   // 0..120
    const int colBase = (tid & 15) * 8;   // 0..120

    // A loader: each thread one float4 along k  (128 rows x 8 k)
    const int aRow = tid >> 1;            // 0..127
    const int aK   = (tid & 1) * 4;       // 0 or 4
    // B loader: each thread one float4 along n  (8 k-rows x 128 n)
    const int bK = tid >> 5;              // 0..7
    const int bN = (tid & 31) * 4;        // 0..124

    const int m0 = blockIdx.y * BM;
    const int n0 = blockIdx.x * BN;

    float acc[8][8];
#pragma unroll
    for (int i = 0; i < 8; i++)
#pragma unroll
        for (int j = 0; j < 8; j++) acc[i][j] = 0.f;

    const float* Aptr = A + (size_t)(m0 + aRow) * lda + aK;
    const float* Bptr = B + (size_t)bK * ldb + n0 + bN;

    // prologue: tile 0 -> buffer 0
    {
        float4 av = *(const float4*)Aptr;
        As[0][aK + 0][aRow] = av.x;
        As[0][aK + 1][aRow] = av.y;
        As[0][aK + 2][aRow] = av.z;
        As[0][aK + 3][aRow] = av.w;
        *(float4*)&Bs[0][bK][bN] = *(const float4*)Bptr;
    }
    __syncthreads();

    const int nkt = K / BK;
    for (int kt = 0; kt < nkt; kt++) {
        float4 av, bv;
        const bool more = (kt + 1 < nkt);
        if (more) {
            av = *(const float4*)(Aptr + (size_t)(kt + 1) * BK);
            bv = *(const float4*)(Bptr + (size_t)(kt + 1) * BK * ldb);
        }
        const int cur = kt & 1;
#pragma unroll
        for (int kk = 0; kk < BK; kk++) {
            float a[8], b[8];
            *(float4*)&a[0] = *(const float4*)&As[cur][kk][rowBase];
            *(float4*)&a[4] = *(const float4*)&As[cur][kk][rowBase + 4];
            *(float4*)&b[0] = *(const float4*)&Bs[cur][kk][colBase];
            *(float4*)&b[4] = *(const float4*)&Bs[cur][kk][colBase + 4];
#pragma unroll
            for (int i = 0; i < 8; i++)
#pragma unroll
                for (int j = 0; j < 8; j++)
                    acc[i][j] += a[i] * b[j];
        }
        if (more) {
            const int nxt = cur ^ 1;
            As[nxt][aK + 0][aRow] = av.x;
            As[nxt][aK + 1][aRow] = av.y;
            As[nxt][aK + 2][aRow] = av.z;
            As[nxt][aK + 3][aRow] = av.w;
            *(float4*)&Bs[nxt][bK][bN] = bv;
        }
        __syncthreads();
    }

#pragma unroll
    for (int i = 0; i < 8; i++) {
        float* Crow = C + (size_t)(m0 + rowBase + i) * ldc + n0 + colBase;
        float4 c0 = make_float4(acc[i][0] * alpha, acc[i][1] * alpha,
                                acc[i][2] * alpha, acc[i][3] * alpha);
        float4 c1 = make_float4(acc[i][4] * alpha, acc[i][5] * alpha,
                                acc[i][6] * alpha, acc[i][7] * alpha);
        *(float4*)&Crow[0] = c0;
        *(float4*)&Crow[4] = c1;
    }
}

// ---------------------------------------------------------------------------
// NT variant: C[M,N] = alpha * A[M,K] @ B[N,K]^T   (both row-major)
// ---------------------------------------------------------------------------
__device__ __forceinline__ void gemm_nt_body(
    const float* __restrict__ A, int lda,
    const float* __restrict__ B, int ldb,
    float* __restrict__ C, int ldc,
    int K, float alpha)
{
    __shared__ float As[2][BK][BM];
    __shared__ float Bs[2][BK][BN];

    const int tid     = threadIdx.x;
    const int rowBase = (tid >> 4) * 8;
    const int colBase = (tid & 15) * 8;

    const int aRow = tid >> 1;
    const int aK   = (tid & 1) * 4;
    const int bRow = tid >> 1;            // n index 0..127
    const int bK4  = (tid & 1) * 4;

    const int m0 = blockIdx.y * BM;
    const int n0 = blockIdx.x * BN;

    float acc[8][8];
#pragma unroll
    for (int i = 0; i < 8; i++)
#pragma unroll
        for (int j = 0; j < 8; j++) acc[i][j] = 0.f;

    const float* Aptr = A + (size_t)(m0 + aRow) * lda + aK;
    const float* Bptr = B + (size_t)(n0 + bRow) * ldb + bK4;

    {
        float4 av = *(const float4*)Aptr;
        As[0][aK + 0][aRow] = av.x;
        As[0][aK + 1][aRow] = av.y;
        As[0][aK + 2][aRow] = av.z;
        As[0][aK + 3][aRow] = av.w;
        float4 bv = *(const float4*)Bptr;
        Bs[0][bK4 + 0][bRow] = bv.x;
        Bs[0][bK4 + 1][bRow] = bv.y;
        Bs[0][bK4 + 2][bRow] = bv.z;
        Bs[0][bK4 + 3][bRow] = bv.w;
    }
    __syncthreads();

    const int nkt = K / BK;
    for (int kt = 0; kt < nkt; kt++) {
        float4 av, bv;
        const bool more = (kt + 1 < nkt);
        if (more) {
            av = *(const float4*)(Aptr + (size_t)(kt + 1) * BK);
            bv = *(const float4*)(Bptr + (size_t)(kt + 1) * BK);
        }
        const int cur = kt & 1;
#pragma unroll
        for (int kk = 0; kk < BK; kk++) {
            float a[8], b[8];
            *(float4*)&a[0] = *(const float4*)&As[cur][kk][rowBase];
            *(float4*)&a[4] = *(const float4*)&As[cur][kk][rowBase + 4];
            *(float4*)&b[0] = *(const float4*)&Bs[cur][kk][colBase];
            *(float4*)&b[4] = *(const float4*)&Bs[cur][kk][colBase + 4];
#pragma unroll
            for (int i = 0; i < 8; i++)
#pragma unroll
                for (int j = 0; j < 8; j++)
                    acc[i][j] += a[i] * b[j];
        }
        if (more) {
            const int nxt = cur ^ 1;
            As[nxt][aK + 0][aRow] = av.x;
            As[nxt][aK + 1][aRow] = av.y;
            As[nxt][aK + 2][aRow] = av.z;
            As[nxt][aK + 3][aRow] = av.w;
            Bs[nxt][bK4 + 0][bRow] = bv.x;
            Bs[nxt][bK4 + 1][bRow] = bv.y;
            Bs[nxt][bK4 + 2][bRow] = bv.z;
            Bs[nxt][bK4 + 3][bRow] = bv.w;
        }
        __syncthreads();
    }

#pragma unroll
    for (int i = 0; i < 8; i++) {
        float* Crow = C + (size_t)(m0 + rowBase + i) * ldc + n0 + colBase;
        float4 c0 = make_float4(acc[i][0] * alpha, acc[i][1] * alpha,
                                acc[i][2] * alpha, acc[i][3] * alpha);
        float4 c1 = make_float4(acc[i][4] * alpha, acc[i][5] * alpha,
                                acc[i][6] * alpha, acc[i][7] * alpha);
        *(float4*)&Crow[0] = c0;
        *(float4*)&Crow[4] = c1;
    }
}

// ---------------------------------------------------------------------------
// Stage kernels
// ---------------------------------------------------------------------------

// 1) qkv = x @ W_qkv   [2048,2048]@[2048,3072]
__global__ void __launch_bounds__(256, 2)
k_qkv(const float* __restrict__ x, const float* __restrict__ Wqkv)
{
    gemm_nn_body(x, DIMC, Wqkv, QKVN, g_qkv, QKVN, DIMC, 1.0f);
}

// 2) scores[h] = (Q_h @ K_{h/4}^T) / sqrt(hd); tiles fully above diagonal skipped
__global__ void __launch_bounds__(256, 2)
k_scores()
{
    if (blockIdx.x > blockIdx.y) return;   // fully-masked tile
    const int h = blockIdx.z;
    const float* Q = g_qkv + h * HD;
    const float* K = g_qkv + KOFF + (h >> 2) * HD;
    float* S = g_scores + (size_t)h * TSEQ * TSEQ;
    gemm_nt_body(Q, QKVN, K, QKVN, S, TSEQ, HD, 0.08838834764831845f /*1/sqrt(128)*/);
}

// 3) causal softmax per row; zero-fills masked region
__global__ void __launch_bounds__(256)
k_softmax()
{
    const int row = blockIdx.x;
    const int h   = blockIdx.y;
    float* p = g_scores + ((size_t)h * TSEQ + row) * TSEQ;
    const int valid = row + 1;
    const int tid = threadIdx.x;
    __shared__ float red[256];

    float m = -1e30f;
    for (int j = tid; j < valid; j += 256) m = fmaxf(m, p[j]);
    red[tid] = m;
    __syncthreads();
#pragma unroll
    for (int s = 128; s > 0; s >>= 1) {
        if (tid < s) red[tid] = fmaxf(red[tid], red[tid + s]);
        __syncthreads();
    }
    m = red[0];
    __syncthreads();

    float sum = 0.f;
    for (int j = tid; j < valid; j += 256) {
        float e = __expf(p[j] - m);
        p[j] = e;
        sum += e;
    }
    red[tid] = sum;
    __syncthreads();
#pragma unroll
    for (int s = 128; s > 0; s >>= 1) {
        if (tid < s) red[tid] += red[tid + s];
        __syncthreads();
    }
    const float inv = 1.0f / red[0];

    for (int j = tid; j < valid; j += 256) p[j] *= inv;
    for (int j = valid + tid; j < TSEQ; j += 256) p[j] = 0.f;
}

// 4) attn_out[:, h*128:+128] = P_h @ V_{h/4}; K-loop bounded by causal limit
__global__ void __launch_bounds__(256, 2)
k_pv()
{
    const int h = blockIdx.z;
    const float* P = g_scores + (size_t)h * TSEQ * TSEQ;
    const float* V = g_qkv + VOFF + (h >> 2) * HD;
    float* O = g_attn + h * HD;
    const int kEff = (blockIdx.y + 1) * BM;   // rows beyond the diag tile are zero
    gemm_nn_body(P, TSEQ, V, QKVN, O, DIMC, kEff < TSEQ ? kEff : TSEQ, 1.0f);
}

// 5) out = attn_out @ W_o
__global__ void __launch_bounds__(256, 2)
k_out(const float* __restrict__ Wo, float* __restrict__ out)
{
    gemm_nn_body(g_attn, DIMC, Wo, DIMC, out, DIMC, DIMC, 1.0f);
}

// ---------------------------------------------------------------------------
extern "C" void kernel_launch(void* const* d_in, const int* in_sizes, int n_in,
                              void* d_out, int out_size)
{
    const float* x    = (const float*)d_in[0];
    const float* Wqkv = (const float*)d_in[1];
    const float* Wo   = (const float*)d_in[2];
    float* out        = (float*)d_out;

    dim3 blk(256);
    k_qkv<<<dim3(QKVN / BN, TSEQ / BM), blk>>>(x, Wqkv);
    k_scores<<<dim3(TSEQ / BN, TSEQ / BM, NH), blk>>>();
    k_softmax<<<dim3(TSEQ, NH), 256>>>();
    k_pv<<<dim3(1, TSEQ / BM, NH), blk>>>();
    k_out<<<dim3(DIMC / BN, TSEQ / BM), blk>>>(Wo, out);
}

// round 3
// speedup vs baseline: 2.9756x; 2.9756x over previous
#include <cuda_runtime.h>
#include <cstdint>
#include <math.h>

// ---------------------------------------------------------------------------
// Problem constants
// ---------------------------------------------------------------------------
#define TSEQ 2048
#define DIMC 2048
#define NH   16
#define NKV  4
#define HD   128
#define QKVN 3072
#define KOFF 2048
#define VOFF 2560

// ---------------------------------------------------------------------------
// Scratch (device globals — allocation-free per harness rules)
// ---------------------------------------------------------------------------
__device__ float g_x[TSEQ * DIMC];                    // tf32-rounded x
__device__ float g_wqkvT[QKVN * DIMC];                // W_qkv^T, rounded
__device__ float g_woT[DIMC * DIMC];                  // W_o^T, rounded
__device__ float g_qkv[TSEQ * QKVN];                  // qkv (rounded)
__device__ float g_vT[NKV * HD * TSEQ];               // 512 x 2048 V^T (rounded)
__device__ float g_scores[(size_t)NH * TSEQ * TSEQ];  // S then P
__device__ float g_attn[TSEQ * DIMC];                 // attn out (rounded)

// ---------------------------------------------------------------------------
// Helpers
// ---------------------------------------------------------------------------
__device__ __forceinline__ uint32_t smem_u32(const void* p) {
    uint32_t a;
    asm("{ .reg .u64 t; cvta.to.shared.u64 t, %1; cvt.u32.u64 %0, t; }" : "=r"(a) : "l"(p));
    return a;
}
__device__ __forceinline__ float rna_tf32(float x) {
    uint32_t u;
    asm("cvt.rna.tf32.f32 %0, %1;" : "=r"(u) : "f"(x));
    return __uint_as_float(u);
}

#define CP_ASYNC16(dst, src) \
    asm volatile("cp.async.cg.shared.global [%0], [%1], 16;" :: "r"(dst), "l"(src) : "memory")
#define CP_COMMIT() asm volatile("cp.async.commit_group;" ::: "memory")
#define CP_WAIT(n)  asm volatile("cp.async.wait_group %0;" :: "n"(n) : "memory")

#define MMA_TF32(c, a, b)                                                      \
    asm volatile(                                                              \
        "mma.sync.aligned.m16n8k8.row.col.f32.tf32.tf32.f32 "                  \
        "{%0,%1,%2,%3}, {%4,%5,%6,%7}, {%8,%9}, {%0,%1,%2,%3};"                \
        : "+f"((c)[0]), "+f"((c)[1]), "+f"((c)[2]), "+f"((c)[3])               \
        : "r"((a)[0]), "r"((a)[1]), "r"((a)[2]), "r"((a)[3]),                  \
          "r"((b)[0]), "r"((b)[1]))

// ---------------------------------------------------------------------------
// Unified tf32 tile GEMM: C[128,128] tile = alpha * A[128,K] @ B[128,K]^T
//   A row-major (lda), B row-major (ldb, K contiguous) -> NT form.
//   causal: skip tiles with bx > by (scores)
//   kclamp: clamp K to (by+1)*128 (PV)
//   z offsets: A += z*sAz, B += (z>>bShift)*sBz, C += z*sCz
// 256 threads, 8 warps (4M x 2N), warp tile 32x64, 4-stage cp.async pipeline.
// ---------------------------------------------------------------------------
#define STAGES 4
#define ABYTES (128 * 32 * 4)
#define STAGEB (2 * ABYTES)

__global__ void __launch_bounds__(256, 1) gemm_mma(
    const float* __restrict__ A, int lda, long sAz,
    const float* __restrict__ B, int ldb, long sBz, int bShift,
    float* __restrict__ C, int ldc, long sCz,
    int K, int causal, int kclamp, float alpha, int roundOut)
{
    extern __shared__ char smem[];
    const uint32_t smemBase = smem_u32(smem);

    const int bx = blockIdx.x, by = blockIdx.y, bz = blockIdx.z;
    if (causal && bx > by) return;
    if (kclamp) { int ke = (by + 1) * 128; K = (ke < K) ? ke : K; }

    A += (size_t)bz * sAz;
    B += (size_t)(bz >> bShift) * sBz;
    C += (size_t)bz * sCz;

    const int m0 = by * 128;
    const int n0 = bx * 128;
    const int tid = threadIdx.x;
    const int wid = tid >> 5, lane = tid & 31;
    const int g = lane >> 2, tg = lane & 3;
    const int wm = (wid & 3) * 32;
    const int wn = (wid >> 2) * 64;

    const int nkt = K >> 5;

    // loader assignments: 1024 16B chunks per operand, 4 per thread
    int lrow[4], lu[4];
    uint32_t lsw[4];
#pragma unroll
    for (int i = 0; i < 4; i++) {
        int id = tid + i * 256;
        lrow[i] = id >> 3;
        lu[i]   = id & 7;
        lsw[i]  = (uint32_t)(lrow[i] * 128 + ((lu[i] ^ (lrow[i] & 7)) << 4));
    }

#define ISSUE_STAGE(kt)                                                        \
    do {                                                                       \
        const uint32_t sA = smemBase + ((kt) & (STAGES - 1)) * STAGEB;         \
        const uint32_t sB = sA + ABYTES;                                       \
        _Pragma("unroll")                                                      \
        for (int i = 0; i < 4; i++) {                                          \
            CP_ASYNC16(sA + lsw[i],                                            \
                       A + (size_t)(m0 + lrow[i]) * lda + (kt) * 32 + lu[i] * 4); \
            CP_ASYNC16(sB + lsw[i],                                            \
                       B + (size_t)(n0 + lrow[i]) * ldb + (kt) * 32 + lu[i] * 4); \
        }                                                                      \
        CP_COMMIT();                                                           \
    } while (0)

    // fragment address precompute (word indices); xor term == g for all rows
    int uoff[8];
#pragma unroll
    for (int u = 0; u < 8; u++) uoff[u] = ((u ^ g) << 2) + tg;
    int rA[4], rB[8];
#pragma unroll
    for (int i = 0; i < 4; i++) rA[i] = (wm + g + i * 8) * 32;
#pragma unroll
    for (int i = 0; i < 8; i++) rB[i] = (wn + i * 8 + g) * 32;

    float acc[2][8][4];
#pragma unroll
    for (int m = 0; m < 2; m++)
#pragma unroll
        for (int n = 0; n < 8; n++)
#pragma unroll
            for (int r = 0; r < 4; r++) acc[m][n][r] = 0.f;

    // prologue
    for (int s = 0; s < STAGES - 1 && s < nkt; s++) ISSUE_STAGE(s);

    for (int kt = 0; kt < nkt; kt++) {
        CP_WAIT(STAGES - 2);
        __syncthreads();
        if (kt + STAGES - 1 < nkt) ISSUE_STAGE(kt + STAGES - 1);

        const uint32_t* sAu =
            (const uint32_t*)(smem + (kt & (STAGES - 1)) * STAGEB);
        const uint32_t* sBu = sAu + (ABYTES / 4);

#pragma unroll
        for (int ks = 0; ks < 4; ks++) {
            const int u0 = uoff[2 * ks], u1 = uoff[2 * ks + 1];
            uint32_t af[2][4];
#pragma unroll
            for (int m = 0; m < 2; m++) {
                af[m][0] = sAu[rA[2 * m + 0] + u0];
                af[m][1] = sAu[rA[2 * m + 1] + u0];
                af[m][2] = sAu[rA[2 * m + 0] + u1];
                af[m][3] = sAu[rA[2 * m + 1] + u1];
            }
            uint32_t bf[8][2];
#pragma unroll
            for (int n = 0; n < 8; n++) {
                bf[n][0] = sBu[rB[n] + u0];
                bf[n][1] = sBu[rB[n] + u1];
            }
#pragma unroll
            for (int m = 0; m < 2; m++)
#pragma unroll
                for (int n = 0; n < 8; n++) MMA_TF32(acc[m][n], af[m], bf[n]);
        }
        __syncthreads();
    }

    // epilogue: direct float2 stores (full 32B sectors)
#pragma unroll
    for (int m = 0; m < 2; m++) {
        const int r0 = m0 + wm + m * 16 + g;
#pragma unroll
        for (int n = 0; n < 8; n++) {
            const int col = n0 + wn + n * 8 + 2 * tg;
            float v0 = acc[m][n][0] * alpha, v1 = acc[m][n][1] * alpha;
            float v2 = acc[m][n][2] * alpha, v3 = acc[m][n][3] * alpha;
            if (roundOut) {
                v0 = rna_tf32(v0); v1 = rna_tf32(v1);
                v2 = rna_tf32(v2); v3 = rna_tf32(v3);
            }
            *(float2*)(C + (size_t)r0 * ldc + col)       = make_float2(v0, v1);
            *(float2*)(C + (size_t)(r0 + 8) * ldc + col) = make_float2(v2, v3);
        }
    }
#undef ISSUE_STAGE
}

// ---------------------------------------------------------------------------
// Elementwise tf32 rounding copy (float4)
// ---------------------------------------------------------------------------
__global__ void k_round4(const float* __restrict__ src, float* __restrict__ dst, int n4)
{
    int i = blockIdx.x * blockDim.x + threadIdx.x;
    if (i >= n4) return;
    float4 v = ((const float4*)src)[i];
    v.x = rna_tf32(v.x); v.y = rna_tf32(v.y);
    v.z = rna_tf32(v.z); v.w = rna_tf32(v.w);
    ((float4*)dst)[i] = v;
}

// ---------------------------------------------------------------------------
// Tiled transpose with tf32 rounding: dst[c][r] = rna(src[r][c])
// grid = (C/32, R/32), block = (32, 8)
// ---------------------------------------------------------------------------
__global__ void k_transpose(const float* __restrict__ src, int lds,
                            float* __restrict__ dst, int ldd)
{
    __shared__ float t[32][33];
    const int c0 = blockIdx.x * 32, r0 = blockIdx.y * 32;
    for (int i = threadIdx.y; i < 32; i += 8)
        t[i][threadIdx.x] = src[(size_t)(r0 + i) * lds + c0 + threadIdx.x];
    __syncthreads();
    for (int i = threadIdx.y; i < 32; i += 8)
        dst[(size_t)(c0 + i) * ldd + r0 + threadIdx.x] = rna_tf32(t[threadIdx.x][i]);
}

// ---------------------------------------------------------------------------
// Causal softmax: per-row, tf32-rounded probs, zero-fill to 128 boundary.
// ---------------------------------------------------------------------------
__global__ void __launch_bounds__(256) k_softmax()
{
    const int row = blockIdx.x;
    const int h   = blockIdx.y;
    float* p = g_scores + ((size_t)h * TSEQ + row) * TSEQ;
    const int valid = row + 1;
    const int fillEnd = ((row >> 7) + 1) << 7;
    const int tid = threadIdx.x;
    __shared__ float red[256];

    float m = -1e30f;
    for (int j = tid; j < valid; j += 256) m = fmaxf(m, p[j]);
    red[tid] = m;
    __syncthreads();
#pragma unroll
    for (int s = 128; s > 0; s >>= 1) {
        if (tid < s) red[tid] = fmaxf(red[tid], red[tid + s]);
        __syncthreads();
    }
    m = red[0];
    __syncthreads();

    float sum = 0.f;
    for (int j = tid; j < valid; j += 256) {
        float e = __expf(p[j] - m);
        p[j] = e;
        sum += e;
    }
    red[tid] = sum;
    __syncthreads();
#pragma unroll
    for (int s = 128; s > 0; s >>= 1) {
        if (tid < s) red[tid] += red[tid + s];
        __syncthreads();
    }
    const float inv = 1.0f / red[0];

    for (int j = tid; j < valid; j += 256) p[j] = rna_tf32(p[j] * inv);
    for (int j = valid + tid; j < fillEnd; j += 256) p[j] = 0.f;
}

// ---------------------------------------------------------------------------
// Host side
// ---------------------------------------------------------------------------
extern "C" void kernel_launch(void* const* d_in, const int* in_sizes, int n_in,
                              void* d_out, int out_size)
{
    const float* x    = (const float*)d_in[0];
    const float* Wqkv = (const float*)d_in[1];
    const float* Wo   = (const float*)d_in[2];
    float* out        = (float*)d_out;

    void *px, *pwqkvT, *pwoT, *pqkv, *pvT, *psc, *pattn;
    cudaGetSymbolAddress(&px, g_x);
    cudaGetSymbolAddress(&pwqkvT, g_wqkvT);
    cudaGetSymbolAddress(&pwoT, g_woT);
    cudaGetSymbolAddress(&pqkv, g_qkv);
    cudaGetSymbolAddress(&pvT, g_vT);
    cudaGetSymbolAddress(&psc, g_scores);
    cudaGetSymbolAddress(&pattn, g_attn);

    const int smemSz = STAGES * STAGEB;   // 128 KB
    static int cfgDone = 0;
    if (!cfgDone) {
        cudaFuncSetAttribute(gemm_mma, cudaFuncAttributeMaxDynamicSharedMemorySize, smemSz);
        cfgDone = 1;
    }

    // 1) tf32-round inputs; transpose+round weights
    k_round4<<<(TSEQ * DIMC / 4 + 255) / 256, 256>>>(x, (float*)px, TSEQ * DIMC / 4);
    k_transpose<<<dim3(QKVN / 32, DIMC / 32), dim3(32, 8)>>>(Wqkv, QKVN, (float*)pwqkvT, DIMC);
    k_transpose<<<dim3(DIMC / 32, DIMC / 32), dim3(32, 8)>>>(Wo, DIMC, (float*)pwoT, DIMC);

    // 2) qkv = x_r @ WqkvT^T  [2048,3072]
    gemm_mma<<<dim3(QKVN / 128, TSEQ / 128, 1), 256, smemSz>>>(
        (const float*)px, DIMC, 0, (const float*)pwqkvT, DIMC, 0, 0,
        (float*)pqkv, QKVN, 0, DIMC, 0, 0, 1.0f, 1);

    // 3) V^T extraction: [2048,512] -> [512,2048]
    k_transpose<<<dim3(512 / 32, TSEQ / 32), dim3(32, 8)>>>(
        (const float*)pqkv + VOFF, QKVN, (float*)pvT, TSEQ);

    // 4) scores = alpha * Q_h K_{h/4}^T  (causal tiles only)
    gemm_mma<<<dim3(TSEQ / 128, TSEQ / 128, NH), 256, smemSz>>>(
        (const float*)pqkv, QKVN, (long)HD,
        (const float*)pqkv + KOFF, QKVN, (long)HD, 2,
        (float*)psc, TSEQ, (long)TSEQ * TSEQ, HD, 1, 0,
        0.08838834764831845f, 0);

    // 5) causal softmax
    k_softmax<<<dim3(TSEQ, NH), 256>>>();

    // 6) attn = P_h @ V_{h/4}  (K clamped by causal bound)
    gemm_mma<<<dim3(1, TSEQ / 128, NH), 256, smemSz>>>(
        (const float*)psc, TSEQ, (long)TSEQ * TSEQ,
        (const float*)pvT, TSEQ, (long)HD * TSEQ, 2,
        (float*)pattn + 0, DIMC, (long)HD, TSEQ, 0, 1, 1.0f, 1);

    // 7) out = attn @ WoT^T
    gemm_mma<<<dim3(DIMC / 128, TSEQ / 128, 1), 256, smemSz>>>(
        (const float*)pattn, DIMC, 0, (const float*)pwoT, DIMC, 0, 0,
        out, DIMC, 0, DIMC, 0, 0, 1.0f, 0);
}

// round 4
// speedup vs baseline: 3.3621x; 1.1299x over previous
#include <cuda_runtime.h>
#include <cstdint>
#include <math.h>

// ---------------------------------------------------------------------------
// Problem constants
// ---------------------------------------------------------------------------
#define TSEQ 2048
#define DIMC 2048
#define NH   16
#define NKV  4
#define HD   128
#define QKVN 3072
#define KOFF 2048
#define VOFF 2560

// ---------------------------------------------------------------------------
// Scratch (device globals — allocation-free per harness rules)
// ---------------------------------------------------------------------------
__device__ float g_x[TSEQ * DIMC];        // tf32-rounded x
__device__ float g_wqkvT[QKVN * DIMC];    // W_qkv^T, rounded
__device__ float g_woT[DIMC * DIMC];      // W_o^T, rounded
__device__ float g_qkv[TSEQ * QKVN];      // qkv (rounded)
__device__ float g_vT[NKV * HD * TSEQ];   // 512 x 2048 V^T (rounded)
__device__ float g_attn[TSEQ * DIMC];     // attn out (rounded)

// ---------------------------------------------------------------------------
// Helpers
// ---------------------------------------------------------------------------
__device__ __forceinline__ uint32_t smem_u32(const void* p) {
    uint32_t a;
    asm("{ .reg .u64 t; cvta.to.shared.u64 t, %1; cvt.u32.u64 %0, t; }" : "=r"(a) : "l"(p));
    return a;
}
__device__ __forceinline__ float rna_tf32(float x) {
    uint32_t u;
    asm("cvt.rna.tf32.f32 %0, %1;" : "=r"(u) : "f"(x));
    return __uint_as_float(u);
}

#define CP_ASYNC16(dst, src) \
    asm volatile("cp.async.cg.shared.global [%0], [%1], 16;" :: "r"(dst), "l"(src) : "memory")
#define CP_COMMIT() asm volatile("cp.async.commit_group;" ::: "memory")
#define CP_WAIT(n)  asm volatile("cp.async.wait_group %0;" :: "n"(n) : "memory")

#define MMA_TF32(c, a, b)                                                      \
    asm volatile(                                                              \
        "mma.sync.aligned.m16n8k8.row.col.f32.tf32.tf32.f32 "                  \
        "{%0,%1,%2,%3}, {%4,%5,%6,%7}, {%8,%9}, {%0,%1,%2,%3};"                \
        : "+f"((c)[0]), "+f"((c)[1]), "+f"((c)[2]), "+f"((c)[3])               \
        : "r"((a)[0]), "r"((a)[1]), "r"((a)[2]), "r"((a)[3]),                  \
          "r"((b)[0]), "r"((b)[1]))

#define STS64F(addr, v0, v1) \
    asm volatile("st.shared.v2.f32 [%0], {%1, %2};" :: "r"(addr), "f"(v0), "f"(v1) : "memory")

// ---------------------------------------------------------------------------
// Dense tf32 tile GEMM (qkv / out projections): C[128,128] = alpha*A@B^T
// 256 threads, 8 warps (4M x 2N), warp tile 32x64, 4-stage cp.async pipeline.
// ---------------------------------------------------------------------------
#define STAGES 4
#define ABYTES (128 * 32 * 4)
#define STAGEB (2 * ABYTES)

__global__ void __launch_bounds__(256, 1) gemm_mma(
    const float* __restrict__ A, int lda,
    const float* __restrict__ B, int ldb,
    float* __restrict__ C, int ldc,
    int K, float alpha, int roundOut)
{
    extern __shared__ char smem[];
    const uint32_t smemBase = smem_u32(smem);

    const int bx = blockIdx.x, by = blockIdx.y;
    const int m0 = by * 128;
    const int n0 = bx * 128;
    const int tid = threadIdx.x;
    const int wid = tid >> 5, lane = tid & 31;
    const int g = lane >> 2, tg = lane & 3;
    const int wm = (wid & 3) * 32;
    const int wn = (wid >> 2) * 64;

    const int nkt = K >> 5;

    int lrow[4], lu[4];
    uint32_t lsw[4];
#pragma unroll
    for (int i = 0; i < 4; i++) {
        int id = tid + i * 256;
        lrow[i] = id >> 3;
        lu[i]   = id & 7;
        lsw[i]  = (uint32_t)(lrow[i] * 128 + ((lu[i] ^ (lrow[i] & 7)) << 4));
    }

#define ISSUE_STAGE(kt)                                                        \
    do {                                                                       \
        const uint32_t sA = smemBase + ((kt) & (STAGES - 1)) * STAGEB;         \
        const uint32_t sB = sA + ABYTES;                                       \
        _Pragma("unroll")                                                      \
        for (int i = 0; i < 4; i++) {                                          \
            CP_ASYNC16(sA + lsw[i],                                            \
                       A + (size_t)(m0 + lrow[i]) * lda + (kt) * 32 + lu[i] * 4); \
            CP_ASYNC16(sB + lsw[i],                                            \
                       B + (size_t)(n0 + lrow[i]) * ldb + (kt) * 32 + lu[i] * 4); \
        }                                                                      \
        CP_COMMIT();                                                           \
    } while (0)

    int uoff[8];
#pragma unroll
    for (int u = 0; u < 8; u++) uoff[u] = ((u ^ g) << 2) + tg;
    int rA[4], rB[8];
#pragma unroll
    for (int i = 0; i < 4; i++) rA[i] = (wm + g + i * 8) * 32;
#pragma unroll
    for (int i = 0; i < 8; i++) rB[i] = (wn + i * 8 + g) * 32;

    float acc[2][8][4];
#pragma unroll
    for (int m = 0; m < 2; m++)
#pragma unroll
        for (int n = 0; n < 8; n++)
#pragma unroll
            for (int r = 0; r < 4; r++) acc[m][n][r] = 0.f;

    for (int s = 0; s < STAGES - 1 && s < nkt; s++) ISSUE_STAGE(s);

    for (int kt = 0; kt < nkt; kt++) {
        CP_WAIT(STAGES - 2);
        __syncthreads();
        if (kt + STAGES - 1 < nkt) ISSUE_STAGE(kt + STAGES - 1);

        const uint32_t* sAu = (const uint32_t*)(smem + (kt & (STAGES - 1)) * STAGEB);
        const uint32_t* sBu = sAu + (ABYTES / 4);

#pragma unroll
        for (int ks = 0; ks < 4; ks++) {
            const int u0 = uoff[2 * ks], u1 = uoff[2 * ks + 1];
            uint32_t af[2][4];
#pragma unroll
            for (int m = 0; m < 2; m++) {
                af[m][0] = sAu[rA[2 * m + 0] + u0];
                af[m][1] = sAu[rA[2 * m + 1] + u0];
                af[m][2] = sAu[rA[2 * m + 0] + u1];
                af[m][3] = sAu[rA[2 * m + 1] + u1];
            }
            uint32_t bf[8][2];
#pragma unroll
            for (int n = 0; n < 8; n++) {
                bf[n][0] = sBu[rB[n] + u0];
                bf[n][1] = sBu[rB[n] + u1];
            }
#pragma unroll
            for (int m = 0; m < 2; m++)
#pragma unroll
                for (int n = 0; n < 8; n++) MMA_TF32(acc[m][n], af[m], bf[n]);
        }
    }

#pragma unroll
    for (int m = 0; m < 2; m++) {
        const int r0 = m0 + wm + m * 16 + g;
#pragma unroll
        for (int n = 0; n < 8; n++) {
            const int col = n0 + wn + n * 8 + 2 * tg;
            float v0 = acc[m][n][0] * alpha, v1 = acc[m][n][1] * alpha;
            float v2 = acc[m][n][2] * alpha, v3 = acc[m][n][3] * alpha;
            if (roundOut) {
                v0 = rna_tf32(v0); v1 = rna_tf32(v1);
                v2 = rna_tf32(v2); v3 = rna_tf32(v3);
            }
            *(float2*)(C + (size_t)r0 * ldc + col)       = make_float2(v0, v1);
            *(float2*)(C + (size_t)(r0 + 8) * ldc + col) = make_float2(v2, v3);
        }
    }
#undef ISSUE_STAGE
}

// ---------------------------------------------------------------------------
// Fused causal flash attention (tf32 mma.sync).
// One CTA per (q-row-tile, head). 8 warps, each owns 16 q rows.
// smem: Qs 64KB (4 chunks) | Ps 64KB (4 chunks) | ring 4x16KB = 192KB total.
// Chunk stream per j-tile: K0..K3 (S mma) then V0..V3 (PV mma), depth-3
// cp.async prefetch so softmax overlaps V loads.
// ---------------------------------------------------------------------------
#define FSM_Q 0
#define FSM_P 65536
#define FSM_R 131072
#define FSM_TOTAL (192 * 1024)

__global__ void __launch_bounds__(256, 1) flash_attn()
{
    extern __shared__ char smem[];
    const uint32_t sb = smem_u32(smem);

    const int h     = blockIdx.y;
    const int itile = (int)gridDim.x - 1 - (int)blockIdx.x;  // heavy-first
    const int kv    = h >> 2;
    const int tid   = threadIdx.x;
    const int lane  = tid & 31;
    const int wid   = tid >> 5;
    const int g     = lane >> 2, tg = lane & 3;
    const int wr    = wid * 16;

    // chunk loader precompute (128 rows x 32 cols, 16B units, 4 per thread)
    int lrow[4], lu4[4];
    uint32_t lsw[4];
#pragma unroll
    for (int i = 0; i < 4; i++) {
        int id = tid + i * 256;
        lrow[i] = id >> 3;
        int lu  = id & 7;
        lu4[i]  = lu * 4;
        lsw[i]  = (uint32_t)(lrow[i] * 128 + ((lu ^ (lrow[i] & 7)) << 4));
    }

    const float* Qg = g_qkv + (size_t)(itile * 128) * QKVN + h * HD;
    const float* Kg = g_qkv + KOFF + (size_t)kv * HD;
    const float* Vg = g_vT + (size_t)(kv * HD) * TSEQ;

    // Q tile: 4 chunks, one commit group
#pragma unroll
    for (int kt = 0; kt < 4; kt++)
#pragma unroll
        for (int i = 0; i < 4; i++)
            CP_ASYNC16(sb + FSM_Q + kt * 16384 + lsw[i],
                       Qg + (size_t)lrow[i] * QKVN + kt * 32 + lu4[i]);
    CP_COMMIT();

    const int nch = 8 * (itile + 1);

#define ISSUE_CHUNK(c)                                                         \
    do {                                                                       \
        const int _jt = (c) >> 3, _ty = ((c) >> 2) & 1, _kt = (c) & 3;         \
        const uint32_t _dst = sb + FSM_R + ((c) & 3) * 16384;                  \
        if (_ty == 0) {                                                        \
            _Pragma("unroll")                                                  \
            for (int i = 0; i < 4; i++)                                        \
                CP_ASYNC16(_dst + lsw[i],                                      \
                           Kg + (size_t)(_jt * 128 + lrow[i]) * QKVN + _kt * 32 + lu4[i]); \
        } else {                                                               \
            _Pragma("unroll")                                                  \
            for (int i = 0; i < 4; i++)                                        \
                CP_ASYNC16(_dst + lsw[i],                                      \
                           Vg + (size_t)lrow[i] * TSEQ + _jt * 128 + _kt * 32 + lu4[i]); \
        }                                                                      \
        CP_COMMIT();                                                           \
    } while (0)

    for (int c = 0; c < 3; c++) ISSUE_CHUNK(c);

    int uoff[8];
#pragma unroll
    for (int u = 0; u < 8; u++) uoff[u] = ((u ^ g) << 2) + tg;
    const int ra0 = (wr + g) * 32;
    const int ra1 = (wr + g + 8) * 32;
    int rb[16];
#pragma unroll
    for (int n = 0; n < 16; n++) rb[n] = (n * 8 + g) * 32;

    float S[16][4], O[16][4];
#pragma unroll
    for (int n = 0; n < 16; n++)
#pragma unroll
        for (int r = 0; r < 4; r++) O[n][r] = 0.f;
    float mrow0 = -1e30f, mrow1 = -1e30f;
    float lsum0 = 0.f, lsum1 = 0.f;

    const int rl0 = wr + g;       // local row (lower half)
    const int rl1 = wr + g + 8;   // local row (upper half)
    const float scl = 0.08838834764831845f;  // 1/sqrt(128)

    for (int c = 0; c < nch; c++) {
        CP_WAIT(2);
        __syncthreads();
        if (c + 3 < nch) ISSUE_CHUNK(c + 3);

        const int jt = c >> 3, ty = (c >> 2) & 1, kt = c & 3;
        const uint32_t* bs = (const uint32_t*)(smem + FSM_R + (c & 3) * 16384);

        if (ty == 0) {
            // ---- S accumulation: A = Q chunk kt, B = K chunk ----
            if (kt == 0) {
#pragma unroll
                for (int n = 0; n < 16; n++)
#pragma unroll
                    for (int r = 0; r < 4; r++) S[n][r] = 0.f;
            }
            const uint32_t* as = (const uint32_t*)(smem + FSM_Q + kt * 16384);
#pragma unroll
            for (int ks = 0; ks < 4; ks++) {
                const int u0 = uoff[2 * ks], u1 = uoff[2 * ks + 1];
                uint32_t af[4];
                af[0] = as[ra0 + u0]; af[1] = as[ra1 + u0];
                af[2] = as[ra0 + u1]; af[3] = as[ra1 + u1];
#pragma unroll
                for (int n = 0; n < 16; n++) {
                    uint32_t bf[2];
                    bf[0] = bs[rb[n] + u0];
                    bf[1] = bs[rb[n] + u1];
                    MMA_TF32(S[n], af, bf);
                }
            }

            if (kt == 3) {
                // ---- online softmax ----
#pragma unroll
                for (int n = 0; n < 16; n++)
#pragma unroll
                    for (int r = 0; r < 4; r++) S[n][r] *= scl;

                if (jt == itile) {   // diagonal tile causal mask
#pragma unroll
                    for (int n = 0; n < 16; n++) {
                        const int c0 = n * 8 + 2 * tg;
                        if (c0 > rl0)     S[n][0] = -1e30f;
                        if (c0 + 1 > rl0) S[n][1] = -1e30f;
                        if (c0 > rl1)     S[n][2] = -1e30f;
                        if (c0 + 1 > rl1) S[n][3] = -1e30f;
                    }
                }

                float tm0 = -1e30f, tm1 = -1e30f;
#pragma unroll
                for (int n = 0; n < 16; n++) {
                    tm0 = fmaxf(tm0, fmaxf(S[n][0], S[n][1]));
                    tm1 = fmaxf(tm1, fmaxf(S[n][2], S[n][3]));
                }
                tm0 = fmaxf(tm0, __shfl_xor_sync(0xFFFFFFFF, tm0, 1));
                tm0 = fmaxf(tm0, __shfl_xor_sync(0xFFFFFFFF, tm0, 2));
                tm1 = fmaxf(tm1, __shfl_xor_sync(0xFFFFFFFF, tm1, 1));
                tm1 = fmaxf(tm1, __shfl_xor_sync(0xFFFFFFFF, tm1, 2));

                const float mn0 = fmaxf(mrow0, tm0);
                const float mn1 = fmaxf(mrow1, tm1);
                const float a0 = __expf(mrow0 - mn0);
                const float a1 = __expf(mrow1 - mn1);
                mrow0 = mn0; mrow1 = mn1;

                float s0 = 0.f, s1 = 0.f;
#pragma unroll
                for (int n = 0; n < 16; n++) {
                    S[n][0] = __expf(S[n][0] - mn0);
                    S[n][1] = __expf(S[n][1] - mn0);
                    S[n][2] = __expf(S[n][2] - mn1);
                    S[n][3] = __expf(S[n][3] - mn1);
                    s0 += S[n][0] + S[n][1];
                    s1 += S[n][2] + S[n][3];
                }
                s0 += __shfl_xor_sync(0xFFFFFFFF, s0, 1);
                s0 += __shfl_xor_sync(0xFFFFFFFF, s0, 2);
                s1 += __shfl_xor_sync(0xFFFFFFFF, s1, 1);
                s1 += __shfl_xor_sync(0xFFFFFFFF, s1, 2);
                lsum0 = lsum0 * a0 + s0;
                lsum1 = lsum1 * a1 + s1;

#pragma unroll
                for (int n = 0; n < 16; n++) {
                    O[n][0] *= a0; O[n][1] *= a0;
                    O[n][2] *= a1; O[n][3] *= a1;
                }

                // write P (tf32-rounded) into Ps chunks
#pragma unroll
                for (int n = 0; n < 16; n++) {
                    const int cf  = n * 8 + 2 * tg;
                    const int pkt = cf >> 5;
                    const int cc  = cf & 31;
                    const uint32_t a =
                        sb + FSM_P + pkt * 16384 + rl0 * 128 +
                        ((((cc >> 2) & 7) ^ g) << 4) + (cc & 3) * 4;
                    STS64F(a, rna_tf32(S[n][0]), rna_tf32(S[n][1]));
                    STS64F(a + 8 * 128, rna_tf32(S[n][2]), rna_tf32(S[n][3]));
                }
            }
        } else {
            // ---- PV accumulation: A = Ps chunk kt, B = V chunk ----
            const uint32_t* as = (const uint32_t*)(smem + FSM_P + kt * 16384);
#pragma unroll
            for (int ks = 0; ks < 4; ks++) {
                const int u0 = uoff[2 * ks], u1 = uoff[2 * ks + 1];
                uint32_t af[4];
                af[0] = as[ra0 + u0]; af[1] = as[ra1 + u0];
                af[2] = as[ra0 + u1]; af[3] = as[ra1 + u1];
#pragma unroll
                for (int n = 0; n < 16; n++) {
                    uint32_t bf[2];
                    bf[0] = bs[rb[n] + u0];
                    bf[1] = bs[rb[n] + u1];
                    MMA_TF32(O[n], af, bf);
                }
            }
        }
    }
#undef ISSUE_CHUNK

    // epilogue: normalize, round, store to g_attn
    const float inv0 = 1.0f / lsum0;
    const float inv1 = 1.0f / lsum1;
    const int gr0 = itile * 128 + rl0;
    const int gr1 = itile * 128 + rl1;
#pragma unroll
    for (int n = 0; n < 16; n++) {
        const int col = h * HD + n * 8 + 2 * tg;
        *(float2*)(g_attn + (size_t)gr0 * DIMC + col) =
            make_float2(rna_tf32(O[n][0] * inv0), rna_tf32(O[n][1] * inv0));
        *(float2*)(g_attn + (size_t)gr1 * DIMC + col) =
            make_float2(rna_tf32(O[n][2] * inv1), rna_tf32(O[n][3] * inv1));
    }
}

// ---------------------------------------------------------------------------
// Elementwise tf32 rounding copy (float4)
// ---------------------------------------------------------------------------
__global__ void k_round4(const float* __restrict__ src, float* __restrict__ dst, int n4)
{
    int i = blockIdx.x * blockDim.x + threadIdx.x;
    if (i >= n4) return;
    float4 v = ((const float4*)src)[i];
    v.x = rna_tf32(v.x); v.y = rna_tf32(v.y);
    v.z = rna_tf32(v.z); v.w = rna_tf32(v.w);
    ((float4*)dst)[i] = v;
}

// ---------------------------------------------------------------------------
// Tiled transpose with tf32 rounding
// ---------------------------------------------------------------------------
__global__ void k_transpose(const float* __restrict__ src, int lds,
                            float* __restrict__ dst, int ldd)
{
    __shared__ float t[32][33];
    const int c0 = blockIdx.x * 32, r0 = blockIdx.y * 32;
    for (int i = threadIdx.y; i < 32; i += 8)
        t[i][threadIdx.x] = src[(size_t)(r0 + i) * lds + c0 + threadIdx.x];
    __syncthreads();
    for (int i = threadIdx.y; i < 32; i += 8)
        dst[(size_t)(c0 + i) * ldd + r0 + threadIdx.x] = rna_tf32(t[threadIdx.x][i]);
}

// ---------------------------------------------------------------------------
// Host side
// ---------------------------------------------------------------------------
extern "C" void kernel_launch(void* const* d_in, const int* in_sizes, int n_in,
                              void* d_out, int out_size)
{
    const float* x    = (const float*)d_in[0];
    const float* Wqkv = (const float*)d_in[1];
    const float* Wo   = (const float*)d_in[2];
    float* out        = (float*)d_out;

    void *px, *pwqkvT, *pwoT, *pqkv, *pvT, *pattn;
    cudaGetSymbolAddress(&px, g_x);
    cudaGetSymbolAddress(&pwqkvT, g_wqkvT);
    cudaGetSymbolAddress(&pwoT, g_woT);
    cudaGetSymbolAddress(&pqkv, g_qkv);
    cudaGetSymbolAddress(&pvT, g_vT);
    cudaGetSymbolAddress(&pattn, g_attn);

    const int smemSz = STAGES * STAGEB;   // 128 KB
    cudaFuncSetAttribute(gemm_mma, cudaFuncAttributeMaxDynamicSharedMemorySize, smemSz);
    cudaFuncSetAttribute(flash_attn, cudaFuncAttributeMaxDynamicSharedMemorySize, FSM_TOTAL);

    // 1) tf32-round inputs; transpose+round weights
    k_round4<<<(TSEQ * DIMC / 4 + 255) / 256, 256>>>(x, (float*)px, TSEQ * DIMC / 4);
    k_transpose<<<dim3(QKVN / 32, DIMC / 32), dim3(32, 8)>>>(Wqkv, QKVN, (float*)pwqkvT, DIMC);
    k_transpose<<<dim3(DIMC / 32, DIMC / 32), dim3(32, 8)>>>(Wo, DIMC, (float*)pwoT, DIMC);

    // 2) qkv = x_r @ WqkvT^T  [2048,3072]
    gemm_mma<<<dim3(QKVN / 128, TSEQ / 128), 256, smemSz>>>(
        (const float*)px, DIMC, (const float*)pwqkvT, DIMC,
        (float*)pqkv, QKVN, DIMC, 1.0f, 1);

    // 3) V^T extraction: [2048,512] -> [512,2048]
    k_transpose<<<dim3(512 / 32, TSEQ / 32), dim3(32, 8)>>>(
        (const float*)pqkv + VOFF, QKVN, (float*)pvT, TSEQ);

    // 4) fused causal attention -> g_attn
    flash_attn<<<dim3(TSEQ / 128, NH), 256, FSM_TOTAL>>>();

    // 5) out = attn @ WoT^T
    gemm_mma<<<dim3(DIMC / 128, TSEQ / 128), 256, smemSz>>>(
        (const float*)pattn, DIMC, (const float*)pwoT, DIMC,
        out, DIMC, DIMC, 1.0f, 0);
}

// round 5
// speedup vs baseline: 3.4108x; 1.0145x over previous
#include <cuda_runtime.h>
#include <cstdint>
#include <math.h>

// ---------------------------------------------------------------------------
// Problem constants
// ---------------------------------------------------------------------------
#define TSEQ 2048
#define DIMC 2048
#define NH   16
#define NKV  4
#define HD   128
#define QKVN 3072
#define KOFF 2048
#define VOFF 2560

// ---------------------------------------------------------------------------
// Scratch (device globals — allocation-free per harness rules)
// ---------------------------------------------------------------------------
__device__ float g_x[TSEQ * DIMC];        // tf32-rounded x
__device__ float g_wqkvT[QKVN * DIMC];    // W_qkv^T, rounded
__device__ float g_woT[DIMC * DIMC];      // W_o^T, rounded
__device__ float g_qkv[TSEQ * QKVN];      // qkv (rounded)
__device__ float g_vT[NKV * HD * TSEQ];   // 512 x 2048 V^T (rounded)
__device__ float g_attn[TSEQ * DIMC];     // attn out (rounded)

// ---------------------------------------------------------------------------
// Helpers
// ---------------------------------------------------------------------------
__device__ __forceinline__ uint32_t smem_u32(const void* p) {
    uint32_t a;
    asm("{ .reg .u64 t; cvta.to.shared.u64 t, %1; cvt.u32.u64 %0, t; }" : "=r"(a) : "l"(p));
    return a;
}
__device__ __forceinline__ float rna_tf32(float x) {
    uint32_t u;
    asm("cvt.rna.tf32.f32 %0, %1;" : "=r"(u) : "f"(x));
    return __uint_as_float(u);
}

#define CP_ASYNC16(dst, src) \
    asm volatile("cp.async.cg.shared.global [%0], [%1], 16;" :: "r"(dst), "l"(src) : "memory")
#define CP_COMMIT() asm volatile("cp.async.commit_group;" ::: "memory")
#define CP_WAIT(n)  asm volatile("cp.async.wait_group %0;" :: "n"(n) : "memory")

#define MMA_TF32(c, a, b)                                                      \
    asm volatile(                                                              \
        "mma.sync.aligned.m16n8k8.row.col.f32.tf32.tf32.f32 "                  \
        "{%0,%1,%2,%3}, {%4,%5,%6,%7}, {%8,%9}, {%0,%1,%2,%3};"                \
        : "+f"((c)[0]), "+f"((c)[1]), "+f"((c)[2]), "+f"((c)[3])               \
        : "r"((a)[0]), "r"((a)[1]), "r"((a)[2]), "r"((a)[3]),                  \
          "r"((b)[0]), "r"((b)[1]))

#define STS64F(addr, v0, v1) \
    asm volatile("st.shared.v2.f32 [%0], {%1, %2};" :: "r"(addr), "f"(v0), "f"(v1) : "memory")

// ---------------------------------------------------------------------------
// Dense tf32 tile GEMM (qkv / out projections): C[128,128] = alpha*A@B^T
// Persistent CTAs, 3-stage cp.async ring (96KB), 2 CTAs/SM, single barrier
// per k-tile (prefetch of slot (kt+2)%3 issued AFTER the barrier).
// ---------------------------------------------------------------------------
#define STAGES 3
#define ABYTES (128 * 32 * 4)
#define STAGEB (2 * ABYTES)

__global__ void __launch_bounds__(256, 2) gemm_mma(
    const float* __restrict__ A, int lda,
    const float* __restrict__ B, int ldb,
    float* __restrict__ C, int ldc,
    int K, int ntx, int ntiles, float alpha, int roundOut)
{
    extern __shared__ char smem[];
    const uint32_t smemBase = smem_u32(smem);

    const int tid = threadIdx.x;
    const int wid = tid >> 5, lane = tid & 31;
    const int g = lane >> 2, tg = lane & 3;
    const int wm = (wid & 3) * 32;
    const int wn = (wid >> 2) * 64;
    const int nkt = K >> 5;

    int lrow[4], lu[4];
    uint32_t lsw[4];
#pragma unroll
    for (int i = 0; i < 4; i++) {
        int id = tid + i * 256;
        lrow[i] = id >> 3;
        lu[i]   = (id & 7) * 4;
        lsw[i]  = (uint32_t)(lrow[i] * 128 + (((id & 7) ^ (lrow[i] & 7)) << 4));
    }

    int uoff[8];
#pragma unroll
    for (int u = 0; u < 8; u++) uoff[u] = ((u ^ g) << 2) + tg;
    int rA[4], rB[8];
#pragma unroll
    for (int i = 0; i < 4; i++) rA[i] = (wm + g + i * 8) * 32;
#pragma unroll
    for (int i = 0; i < 8; i++) rB[i] = (wn + i * 8 + g) * 32;

    for (int t = blockIdx.x; t < ntiles; t += gridDim.x) {
        const int bx = t % ntx, by = t / ntx;
        const int m0 = by * 128;
        const int n0 = bx * 128;

#define ISSUE_STAGE(kt)                                                        \
    do {                                                                       \
        const int _sl = (kt) % STAGES;                                         \
        const uint32_t sA = smemBase + _sl * STAGEB;                           \
        const uint32_t sB = sA + ABYTES;                                       \
        _Pragma("unroll")                                                      \
        for (int i = 0; i < 4; i++) {                                          \
            CP_ASYNC16(sA + lsw[i],                                            \
                       A + (size_t)(m0 + lrow[i]) * lda + (kt) * 32 + lu[i]);  \
            CP_ASYNC16(sB + lsw[i],                                            \
                       B + (size_t)(n0 + lrow[i]) * ldb + (kt) * 32 + lu[i]);  \
        }                                                                      \
        CP_COMMIT();                                                           \
    } while (0)

        float acc[2][8][4];
#pragma unroll
        for (int m = 0; m < 2; m++)
#pragma unroll
            for (int n = 0; n < 8; n++)
#pragma unroll
                for (int r = 0; r < 4; r++) acc[m][n][r] = 0.f;

        __syncthreads();   // previous tile's readers done before ring reuse
        ISSUE_STAGE(0);
        ISSUE_STAGE(1);

        for (int kt = 0; kt < nkt; kt++) {
            if (kt + 1 < nkt) { CP_WAIT(1); } else { CP_WAIT(0); }
            __syncthreads();
            if (kt + 2 < nkt) ISSUE_STAGE(kt + 2);   // after barrier: safe slot reuse

            const uint32_t* sAu = (const uint32_t*)(smem + (kt % STAGES) * STAGEB);
            const uint32_t* sBu = sAu + (ABYTES / 4);

#pragma unroll
            for (int ks = 0; ks < 4; ks++) {
                const int u0 = uoff[2 * ks], u1 = uoff[2 * ks + 1];
                uint32_t af[2][4];
#pragma unroll
                for (int m = 0; m < 2; m++) {
                    af[m][0] = sAu[rA[2 * m + 0] + u0];
                    af[m][1] = sAu[rA[2 * m + 1] + u0];
                    af[m][2] = sAu[rA[2 * m + 0] + u1];
                    af[m][3] = sAu[rA[2 * m + 1] + u1];
                }
                uint32_t bf[8][2];
#pragma unroll
                for (int n = 0; n < 8; n++) {
                    bf[n][0] = sBu[rB[n] + u0];
                    bf[n][1] = sBu[rB[n] + u1];
                }
#pragma unroll
                for (int m = 0; m < 2; m++)
#pragma unroll
                    for (int n = 0; n < 8; n++) MMA_TF32(acc[m][n], af[m], bf[n]);
            }
        }

#pragma unroll
        for (int m = 0; m < 2; m++) {
            const int r0 = m0 + wm + m * 16 + g;
#pragma unroll
            for (int n = 0; n < 8; n++) {
                const int col = n0 + wn + n * 8 + 2 * tg;
                float v0 = acc[m][n][0] * alpha, v1 = acc[m][n][1] * alpha;
                float v2 = acc[m][n][2] * alpha, v3 = acc[m][n][3] * alpha;
                if (roundOut) {
                    v0 = rna_tf32(v0); v1 = rna_tf32(v1);
                    v2 = rna_tf32(v2); v3 = rna_tf32(v3);
                }
                *(float2*)(C + (size_t)r0 * ldc + col)       = make_float2(v0, v1);
                *(float2*)(C + (size_t)(r0 + 8) * ldc + col) = make_float2(v2, v3);
            }
        }
#undef ISSUE_STAGE
    }
}

// ---------------------------------------------------------------------------
// Fused causal flash attention (tf32 mma.sync). Unchanged from round 4.
// ---------------------------------------------------------------------------
#define FSM_Q 0
#define FSM_P 65536
#define FSM_R 131072
#define FSM_TOTAL (192 * 1024)

__global__ void __launch_bounds__(256, 1) flash_attn()
{
    extern __shared__ char smem[];
    const uint32_t sb = smem_u32(smem);

    const int h     = blockIdx.y;
    const int itile = (int)gridDim.x - 1 - (int)blockIdx.x;  // heavy-first
    const int kv    = h >> 2;
    const int tid   = threadIdx.x;
    const int lane  = tid & 31;
    const int wid   = tid >> 5;
    const int g     = lane >> 2, tg = lane & 3;
    const int wr    = wid * 16;

    int lrow[4], lu4[4];
    uint32_t lsw[4];
#pragma unroll
    for (int i = 0; i < 4; i++) {
        int id = tid + i * 256;
        lrow[i] = id >> 3;
        int lu  = id & 7;
        lu4[i]  = lu * 4;
        lsw[i]  = (uint32_t)(lrow[i] * 128 + ((lu ^ (lrow[i] & 7)) << 4));
    }

    const float* Qg = g_qkv + (size_t)(itile * 128) * QKVN + h * HD;
    const float* Kg = g_qkv + KOFF + (size_t)kv * HD;
    const float* Vg = g_vT + (size_t)(kv * HD) * TSEQ;

#pragma unroll
    for (int kt = 0; kt < 4; kt++)
#pragma unroll
        for (int i = 0; i < 4; i++)
            CP_ASYNC16(sb + FSM_Q + kt * 16384 + lsw[i],
                       Qg + (size_t)lrow[i] * QKVN + kt * 32 + lu4[i]);
    CP_COMMIT();

    const int nch = 8 * (itile + 1);

#define ISSUE_CHUNK(c)                                                         \
    do {                                                                       \
        const int _jt = (c) >> 3, _ty = ((c) >> 2) & 1, _kt = (c) & 3;         \
        const uint32_t _dst = sb + FSM_R + ((c) & 3) * 16384;                  \
        if (_ty == 0) {                                                        \
            _Pragma("unroll")                                                  \
            for (int i = 0; i < 4; i++)                                        \
                CP_ASYNC16(_dst + lsw[i],                                      \
                           Kg + (size_t)(_jt * 128 + lrow[i]) * QKVN + _kt * 32 + lu4[i]); \
        } else {                                                               \
            _Pragma("unroll")                                                  \
            for (int i = 0; i < 4; i++)                                        \
                CP_ASYNC16(_dst + lsw[i],                                      \
                           Vg + (size_t)lrow[i] * TSEQ + _jt * 128 + _kt * 32 + lu4[i]); \
        }                                                                      \
        CP_COMMIT();                                                           \
    } while (0)

    for (int c = 0; c < 3; c++) ISSUE_CHUNK(c);

    int uoff[8];
#pragma unroll
    for (int u = 0; u < 8; u++) uoff[u] = ((u ^ g) << 2) + tg;
    const int ra0 = (wr + g) * 32;
    const int ra1 = (wr + g + 8) * 32;
    int rb[16];
#pragma unroll
    for (int n = 0; n < 16; n++) rb[n] = (n * 8 + g) * 32;

    float S[16][4], O[16][4];
#pragma unroll
    for (int n = 0; n < 16; n++)
#pragma unroll
        for (int r = 0; r < 4; r++) O[n][r] = 0.f;
    float mrow0 = -1e30f, mrow1 = -1e30f;
    float lsum0 = 0.f, lsum1 = 0.f;

    const int rl0 = wr + g;
    const int rl1 = wr + g + 8;
    const float scl = 0.08838834764831845f;

    for (int c = 0; c < nch; c++) {
        CP_WAIT(2);
        __syncthreads();
        if (c + 3 < nch) ISSUE_CHUNK(c + 3);

        const int jt = c >> 3, ty = (c >> 2) & 1, kt = c & 3;
        const uint32_t* bs = (const uint32_t*)(smem + FSM_R + (c & 3) * 16384);

        if (ty == 0) {
            if (kt == 0) {
#pragma unroll
                for (int n = 0; n < 16; n++)
#pragma unroll
                    for (int r = 0; r < 4; r++) S[n][r] = 0.f;
            }
            const uint32_t* as = (const uint32_t*)(smem + FSM_Q + kt * 16384);
#pragma unroll
            for (int ks = 0; ks < 4; ks++) {
                const int u0 = uoff[2 * ks], u1 = uoff[2 * ks + 1];
                uint32_t af[4];
                af[0] = as[ra0 + u0]; af[1] = as[ra1 + u0];
                af[2] = as[ra0 + u1]; af[3] = as[ra1 + u1];
#pragma unroll
                for (int n = 0; n < 16; n++) {
                    uint32_t bf[2];
                    bf[0] = bs[rb[n] + u0];
                    bf[1] = bs[rb[n] + u1];
                    MMA_TF32(S[n], af, bf);
                }
            }

            if (kt == 3) {
#pragma unroll
                for (int n = 0; n < 16; n++)
#pragma unroll
                    for (int r = 0; r < 4; r++) S[n][r] *= scl;

                if (jt == itile) {
#pragma unroll
                    for (int n = 0; n < 16; n++) {
                        const int c0 = n * 8 + 2 * tg;
                        if (c0 > rl0)     S[n][0] = -1e30f;
                        if (c0 + 1 > rl0) S[n][1] = -1e30f;
                        if (c0 > rl1)     S[n][2] = -1e30f;
                        if (c0 + 1 > rl1) S[n][3] = -1e30f;
                    }
                }

                float tm0 = -1e30f, tm1 = -1e30f;
#pragma unroll
                for (int n = 0; n < 16; n++) {
                    tm0 = fmaxf(tm0, fmaxf(S[n][0], S[n][1]));
                    tm1 = fmaxf(tm1, fmaxf(S[n][2], S[n][3]));
                }
                tm0 = fmaxf(tm0, __shfl_xor_sync(0xFFFFFFFF, tm0, 1));
                tm0 = fmaxf(tm0, __shfl_xor_sync(0xFFFFFFFF, tm0, 2));
                tm1 = fmaxf(tm1, __shfl_xor_sync(0xFFFFFFFF, tm1, 1));
                tm1 = fmaxf(tm1, __shfl_xor_sync(0xFFFFFFFF, tm1, 2));

                const float mn0 = fmaxf(mrow0, tm0);
                const float mn1 = fmaxf(mrow1, tm1);
                const float a0 = __expf(mrow0 - mn0);
                const float a1 = __expf(mrow1 - mn1);
                mrow0 = mn0; mrow1 = mn1;

                float s0 = 0.f, s1 = 0.f;
#pragma unroll
                for (int n = 0; n < 16; n++) {
                    S[n][0] = __expf(S[n][0] - mn0);
                    S[n][1] = __expf(S[n][1] - mn0);
                    S[n][2] = __expf(S[n][2] - mn1);
                    S[n][3] = __expf(S[n][3] - mn1);
                    s0 += S[n][0] + S[n][1];
                    s1 += S[n][2] + S[n][3];
                }
                s0 += __shfl_xor_sync(0xFFFFFFFF, s0, 1);
                s0 += __shfl_xor_sync(0xFFFFFFFF, s0, 2);
                s1 += __shfl_xor_sync(0xFFFFFFFF, s1, 1);
                s1 += __shfl_xor_sync(0xFFFFFFFF, s1, 2);
                lsum0 = lsum0 * a0 + s0;
                lsum1 = lsum1 * a1 + s1;

#pragma unroll
                for (int n = 0; n < 16; n++) {
                    O[n][0] *= a0; O[n][1] *= a0;
                    O[n][2] *= a1; O[n][3] *= a1;
                }

#pragma unroll
                for (int n = 0; n < 16; n++) {
                    const int cf  = n * 8 + 2 * tg;
                    const int pkt = cf >> 5;
                    const int cc  = cf & 31;
                    const uint32_t a =
                        sb + FSM_P + pkt * 16384 + rl0 * 128 +
                        ((((cc >> 2) & 7) ^ g) << 4) + (cc & 3) * 4;
                    STS64F(a, rna_tf32(S[n][0]), rna_tf32(S[n][1]));
                    STS64F(a + 8 * 128, rna_tf32(S[n][2]), rna_tf32(S[n][3]));
                }
            }
        } else {
            const uint32_t* as = (const uint32_t*)(smem + FSM_P + kt * 16384);
#pragma unroll
            for (int ks = 0; ks < 4; ks++) {
                const int u0 = uoff[2 * ks], u1 = uoff[2 * ks + 1];
                uint32_t af[4];
                af[0] = as[ra0 + u0]; af[1] = as[ra1 + u0];
                af[2] = as[ra0 + u1]; af[3] = as[ra1 + u1];
#pragma unroll
                for (int n = 0; n < 16; n++) {
                    uint32_t bf[2];
                    bf[0] = bs[rb[n] + u0];
                    bf[1] = bs[rb[n] + u1];
                    MMA_TF32(O[n], af, bf);
                }
            }
        }
    }
#undef ISSUE_CHUNK

    const float inv0 = 1.0f / lsum0;
    const float inv1 = 1.0f / lsum1;
    const int gr0 = itile * 128 + rl0;
    const int gr1 = itile * 128 + rl1;
#pragma unroll
    for (int n = 0; n < 16; n++) {
        const int col = h * HD + n * 8 + 2 * tg;
        *(float2*)(g_attn + (size_t)gr0 * DIMC + col) =
            make_float2(rna_tf32(O[n][0] * inv0), rna_tf32(O[n][1] * inv0));
        *(float2*)(g_attn + (size_t)gr1 * DIMC + col) =
            make_float2(rna_tf32(O[n][2] * inv1), rna_tf32(O[n][3] * inv1));
    }
}

// ---------------------------------------------------------------------------
// Elementwise tf32 rounding copy (float4)
// ---------------------------------------------------------------------------
__global__ void k_round4(const float* __restrict__ src, float* __restrict__ dst, int n4)
{
    int i = blockIdx.x * blockDim.x + threadIdx.x;
    if (i >= n4) return;
    float4 v = ((const float4*)src)[i];
    v.x = rna_tf32(v.x); v.y = rna_tf32(v.y);
    v.z = rna_tf32(v.z); v.w = rna_tf32(v.w);
    ((float4*)dst)[i] = v;
}

// ---------------------------------------------------------------------------
// Tiled transpose with tf32 rounding
// ---------------------------------------------------------------------------
__global__ void k_transpose(const float* __restrict__ src, int lds,
                            float* __restrict__ dst, int ldd)
{
    __shared__ float t[32][33];
    const int c0 = blockIdx.x * 32, r0 = blockIdx.y * 32;
    for (int i = threadIdx.y; i < 32; i += 8)
        t[i][threadIdx.x] = src[(size_t)(r0 + i) * lds + c0 + threadIdx.x];
    __syncthreads();
    for (int i = threadIdx.y; i < 32; i += 8)
        dst[(size_t)(c0 + i) * ldd + r0 + threadIdx.x] = rna_tf32(t[threadIdx.x][i]);
}

// ---------------------------------------------------------------------------
// Host side
// ---------------------------------------------------------------------------
extern "C" void kernel_launch(void* const* d_in, const int* in_sizes, int n_in,
                              void* d_out, int out_size)
{
    const float* x    = (const float*)d_in[0];
    const float* Wqkv = (const float*)d_in[1];
    const float* Wo   = (const float*)d_in[2];
    float* out        = (float*)d_out;

    void *px, *pwqkvT, *pwoT, *pqkv, *pvT, *pattn;
    cudaGetSymbolAddress(&px, g_x);
    cudaGetSymbolAddress(&pwqkvT, g_wqkvT);
    cudaGetSymbolAddress(&pwoT, g_woT);
    cudaGetSymbolAddress(&pqkv, g_qkv);
    cudaGetSymbolAddress(&pvT, g_vT);
    cudaGetSymbolAddress(&pattn, g_attn);

    const int smemSz = STAGES * STAGEB;   // 96 KB
    cudaFuncSetAttribute(gemm_mma, cudaFuncAttributeMaxDynamicSharedMemorySize, smemSz);
    cudaFuncSetAttribute(flash_attn, cudaFuncAttributeMaxDynamicSharedMemorySize, FSM_TOTAL);

    int smCount = 148;
    cudaDeviceGetAttribute(&smCount, cudaDevAttrMultiProcessorCount, 0);

    // 1) tf32-round inputs; transpose+round weights
    k_round4<<<(TSEQ * DIMC / 4 + 255) / 256, 256>>>(x, (float*)px, TSEQ * DIMC / 4);
    k_transpose<<<dim3(QKVN / 32, DIMC / 32), dim3(32, 8)>>>(Wqkv, QKVN, (float*)pwqkvT, DIMC);
    k_transpose<<<dim3(DIMC / 32, DIMC / 32), dim3(32, 8)>>>(Wo, DIMC, (float*)pwoT, DIMC);

    // 2) qkv = x_r @ WqkvT^T  [2048,3072]  (persistent, 2 CTA/SM)
    {
        const int ntx = QKVN / 128, ntiles = ntx * (TSEQ / 128);
        const int grid = (ntiles < 2 * smCount) ? ntiles : 2 * smCount;
        gemm_mma<<<grid, 256, smemSz>>>(
            (const float*)px, DIMC, (const float*)pwqkvT, DIMC,
            (float*)pqkv, QKVN, DIMC, ntx, ntiles, 1.0f, 1);
    }

    // 3) V^T extraction: [2048,512] -> [512,2048]
    k_transpose<<<dim3(512 / 32, TSEQ / 32), dim3(32, 8)>>>(
        (const float*)pqkv + VOFF, QKVN, (float*)pvT, TSEQ);

    // 4) fused causal attention -> g_attn
    flash_attn<<<dim3(TSEQ / 128, NH), 256, FSM_TOTAL>>>();

    // 5) out = attn @ WoT^T
    {
        const int ntx = DIMC / 128, ntiles = ntx * (TSEQ / 128);
        const int grid = (ntiles < 2 * smCount) ? ntiles : 2 * smCount;
        gemm_mma<<<grid, 256, smemSz>>>(
            (const float*)pattn, DIMC, (const float*)pwoT, DIMC,
            out, DIMC, DIMC, ntx, ntiles, 1.0f, 0);
    }
}

// round 6
// speedup vs baseline: 3.4198x; 1.0026x over previous
#include <cuda_runtime.h>
#include <cstdint>
#include <math.h>

// ---------------------------------------------------------------------------
// Problem constants
// ---------------------------------------------------------------------------
#define TSEQ 2048
#define DIMC 2048
#define NH   16
#define NKV  4
#define HD   128
#define QKVN 3072
#define KOFF 2048
#define VOFF 2560

// ---------------------------------------------------------------------------
// Scratch (device globals — allocation-free per harness rules)
// ---------------------------------------------------------------------------
__device__ float g_x[TSEQ * DIMC];
__device__ float g_wqkvT[QKVN * DIMC];
__device__ float g_woT[DIMC * DIMC];
__device__ float g_qkv[TSEQ * QKVN];
__device__ float g_vT[NKV * HD * TSEQ];
__device__ float g_attn[TSEQ * DIMC];

// ---------------------------------------------------------------------------
// Helpers
// ---------------------------------------------------------------------------
__device__ __forceinline__ uint32_t smem_u32(const void* p) {
    uint32_t a;
    asm("{ .reg .u64 t; cvta.to.shared.u64 t, %1; cvt.u32.u64 %0, t; }" : "=r"(a) : "l"(p));
    return a;
}
__device__ __forceinline__ float rna_tf32(float x) {
    uint32_t u;
    asm("cvt.rna.tf32.f32 %0, %1;" : "=r"(u) : "f"(x));
    return __uint_as_float(u);
}

#define CP_ASYNC16(dst, src) \
    asm volatile("cp.async.cg.shared.global [%0], [%1], 16;" :: "r"(dst), "l"(src) : "memory")
#define CP_COMMIT() asm volatile("cp.async.commit_group;" ::: "memory")
#define CP_WAIT(n)  asm volatile("cp.async.wait_group %0;" :: "n"(n) : "memory")

#define MMA_TF32(c, a, b)                                                      \
    asm volatile(                                                              \
        "mma.sync.aligned.m16n8k8.row.col.f32.tf32.tf32.f32 "                  \
        "{%0,%1,%2,%3}, {%4,%5,%6,%7}, {%8,%9}, {%0,%1,%2,%3};"                \
        : "+f"((c)[0]), "+f"((c)[1]), "+f"((c)[2]), "+f"((c)[3])               \
        : "r"((a)[0]), "r"((a)[1]), "r"((a)[2]), "r"((a)[3]),                  \
          "r"((b)[0]), "r"((b)[1]))

// ldmatrix x4: thread t gets element (t&3) of row (t>>2) of matrix j in reg j.
#define LDSM_X4(r, addr)                                                       \
    asm volatile("ldmatrix.sync.aligned.m8n8.x4.shared.b16 {%0,%1,%2,%3}, [%4];" \
        : "=r"((r)[0]), "=r"((r)[1]), "=r"((r)[2]), "=r"((r)[3]) : "r"(addr))

#define STS64F(addr, v0, v1) \
    asm volatile("st.shared.v2.f32 [%0], {%1, %2};" :: "r"(addr), "f"(v0), "f"(v1) : "memory")

// ---------------------------------------------------------------------------
// Dense tf32 tile GEMM: C[128,128] = alpha * A[128,K] @ B[128,K]^T
// 256 threads, 8 warps (4M x 2N), warp tile 32x64, 4-stage cp.async ring.
// Fragment loads via ldmatrix.x4.
// ---------------------------------------------------------------------------
#define STAGES 4
#define ABYTES (128 * 32 * 4)
#define STAGEB (2 * ABYTES)

__global__ void __launch_bounds__(256, 1) gemm_mma(
    const float* __restrict__ A, int lda,
    const float* __restrict__ B, int ldb,
    float* __restrict__ C, int ldc,
    int K, float alpha, int roundOut)
{
    extern __shared__ char smem[];
    const uint32_t smemBase = smem_u32(smem);

    const int bx = blockIdx.x, by = blockIdx.y;
    const int m0 = by * 128;
    const int n0 = bx * 128;
    const int tid = threadIdx.x;
    const int wid = tid >> 5, lane = tid & 31;
    const int g = lane >> 2, tg = lane & 3;
    const int wm = (wid & 3) * 32;
    const int wn = (wid >> 2) * 64;
    const int nkt = K >> 5;

    // cp.async loader: 1024 16B chunks per operand, 4 per thread
    int lrow[4], lu4[4];
    uint32_t lsw[4];
#pragma unroll
    for (int i = 0; i < 4; i++) {
        int id = tid + i * 256;
        lrow[i] = id >> 3;
        lu4[i]  = (id & 7) * 4;
        lsw[i]  = (uint32_t)(lrow[i] * 128 + (((id & 7) ^ (lrow[i] & 7)) << 4));
    }

#define ISSUE_STAGE(kt)                                                        \
    do {                                                                       \
        const uint32_t sA = smemBase + ((kt) & (STAGES - 1)) * STAGEB;         \
        const uint32_t sB = sA + ABYTES;                                       \
        _Pragma("unroll")                                                      \
        for (int i = 0; i < 4; i++) {                                          \
            CP_ASYNC16(sA + lsw[i],                                            \
                       A + (size_t)(m0 + lrow[i]) * lda + (kt) * 32 + lu4[i]); \
            CP_ASYNC16(sB + lsw[i],                                            \
                       B + (size_t)(n0 + lrow[i]) * ldb + (kt) * 32 + lu4[i]); \
        }                                                                      \
        CP_COMMIT();                                                           \
    } while (0)

    // ldmatrix address precompute (byte offsets inside operand tile)
    const int r7  = lane & 7;
    const int b3  = (lane >> 3) & 1;   // matrix-pair selector bit
    const int b4  = (lane >> 4) & 1;
    uint32_t rowA[2], rowB[4], unitA[4], unitB[4];
#pragma unroll
    for (int m = 0; m < 2; m++) rowA[m] = (uint32_t)((wm + m * 16 + b3 * 8 + r7) * 128);
#pragma unroll
    for (int p = 0; p < 4; p++) rowB[p] = (uint32_t)((wn + (2 * p + b4) * 8 + r7) * 128);
#pragma unroll
    for (int ks = 0; ks < 4; ks++) {
        unitA[ks] = (uint32_t)(((2 * ks + b4) ^ r7) << 4);
        unitB[ks] = (uint32_t)(((2 * ks + b3) ^ r7) << 4);
    }

    float acc[2][8][4];
#pragma unroll
    for (int m = 0; m < 2; m++)
#pragma unroll
        for (int n = 0; n < 8; n++)
#pragma unroll
            for (int q = 0; q < 4; q++) acc[m][n][q] = 0.f;

    for (int s = 0; s < STAGES - 1 && s < nkt; s++) ISSUE_STAGE(s);

    for (int kt = 0; kt < nkt; kt++) {
        CP_WAIT(STAGES - 2);
        __syncthreads();
        if (kt + STAGES - 1 < nkt) ISSUE_STAGE(kt + STAGES - 1);

        const uint32_t sA = smemBase + (kt & (STAGES - 1)) * STAGEB;
        const uint32_t sB = sA + ABYTES;

#pragma unroll
        for (int ks = 0; ks < 4; ks++) {
            uint32_t af[2][4];
            LDSM_X4(af[0], sA + rowA[0] + unitA[ks]);
            LDSM_X4(af[1], sA + rowA[1] + unitA[ks]);
            uint32_t bfr[4][4];
#pragma unroll
            for (int p = 0; p < 4; p++) LDSM_X4(bfr[p], sB + rowB[p] + unitB[ks]);
#pragma unroll
            for (int m = 0; m < 2; m++)
#pragma unroll
                for (int n = 0; n < 8; n++)
                    MMA_TF32(acc[m][n], af[m], &bfr[n >> 1][(n & 1) * 2]);
        }
    }

#pragma unroll
    for (int m = 0; m < 2; m++) {
        const int r0 = m0 + wm + m * 16 + g;
#pragma unroll
        for (int n = 0; n < 8; n++) {
            const int col = n0 + wn + n * 8 + 2 * tg;
            float v0 = acc[m][n][0] * alpha, v1 = acc[m][n][1] * alpha;
            float v2 = acc[m][n][2] * alpha, v3 = acc[m][n][3] * alpha;
            if (roundOut) {
                v0 = rna_tf32(v0); v1 = rna_tf32(v1);
                v2 = rna_tf32(v2); v3 = rna_tf32(v3);
            }
            *(float2*)(C + (size_t)r0 * ldc + col)       = make_float2(v0, v1);
            *(float2*)(C + (size_t)(r0 + 8) * ldc + col) = make_float2(v2, v3);
        }
    }
#undef ISSUE_STAGE
}

// ---------------------------------------------------------------------------
// Fused causal flash attention (tf32 mma.sync, ldmatrix fragments).
// One CTA per (q-row-tile, head). 8 warps x 16 q rows.
// smem: Qs 64KB | Ps 64KB | ring 4x16KB = 192KB.
// ---------------------------------------------------------------------------
#define FSM_Q 0
#define FSM_P 65536
#define FSM_R 131072
#define FSM_TOTAL (192 * 1024)

__global__ void __launch_bounds__(256, 1) flash_attn()
{
    extern __shared__ char smem[];
    const uint32_t sb = smem_u32(smem);

    const int h     = blockIdx.y;
    const int itile = (int)gridDim.x - 1 - (int)blockIdx.x;
    const int kvh   = h >> 2;
    const int tid   = threadIdx.x;
    const int lane  = tid & 31;
    const int wid   = tid >> 5;
    const int g     = lane >> 2, tg = lane & 3;
    const int wr    = wid * 16;

    int lrow[4], lu4[4];
    uint32_t lsw[4];
#pragma unroll
    for (int i = 0; i < 4; i++) {
        int id = tid + i * 256;
        lrow[i] = id >> 3;
        lu4[i]  = (id & 7) * 4;
        lsw[i]  = (uint32_t)(lrow[i] * 128 + (((id & 7) ^ (lrow[i] & 7)) << 4));
    }

    const float* Qg = g_qkv + (size_t)(itile * 128) * QKVN + h * HD;
    const float* Kg = g_qkv + KOFF + (size_t)kvh * HD;
    const float* Vg = g_vT + (size_t)(kvh * HD) * TSEQ;

#pragma unroll
    for (int kt = 0; kt < 4; kt++)
#pragma unroll
        for (int i = 0; i < 4; i++)
            CP_ASYNC16(sb + FSM_Q + kt * 16384 + lsw[i],
                       Qg + (size_t)lrow[i] * QKVN + kt * 32 + lu4[i]);
    CP_COMMIT();

    const int nch = 8 * (itile + 1);

#define ISSUE_CHUNK(c)                                                         \
    do {                                                                       \
        const int _jt = (c) >> 3, _ty = ((c) >> 2) & 1, _kt = (c) & 3;         \
        const uint32_t _dst = sb + FSM_R + ((c) & 3) * 16384;                  \
        if (_ty == 0) {                                                        \
            _Pragma("unroll")                                                  \
            for (int i = 0; i < 4; i++)                                        \
                CP_ASYNC16(_dst + lsw[i],                                      \
                           Kg + (size_t)(_jt * 128 + lrow[i]) * QKVN + _kt * 32 + lu4[i]); \
        } else {                                                               \
            _Pragma("unroll")                                                  \
            for (int i = 0; i < 4; i++)                                        \
                CP_ASYNC16(_dst + lsw[i],                                      \
                           Vg + (size_t)lrow[i] * TSEQ + _jt * 128 + _kt * 32 + lu4[i]); \
        }                                                                      \
        CP_COMMIT();                                                           \
    } while (0)

    for (int c = 0; c < 3; c++) ISSUE_CHUNK(c);

    // ldmatrix address precompute
    const int r7 = lane & 7;
    const int b3 = (lane >> 3) & 1;
    const int b4 = (lane >> 4) & 1;
    const uint32_t rowAf = (uint32_t)((wr + b3 * 8 + r7) * 128);
    uint32_t rowB[8], unitA[4], unitB[4];
#pragma unroll
    for (int p = 0; p < 8; p++) rowB[p] = (uint32_t)(((2 * p + b4) * 8 + r7) * 128);
#pragma unroll
    for (int ks = 0; ks < 4; ks++) {
        unitA[ks] = (uint32_t)(((2 * ks + b4) ^ r7) << 4);
        unitB[ks] = (uint32_t)(((2 * ks + b3) ^ r7) << 4);
    }

    float S[16][4], O[16][4];
#pragma unroll
    for (int n = 0; n < 16; n++)
#pragma unroll
        for (int q = 0; q < 4; q++) O[n][q] = 0.f;
    float mrow0 = -1e30f, mrow1 = -1e30f;
    float lsum0 = 0.f, lsum1 = 0.f;

    const int rl0 = wr + g;
    const int rl1 = wr + g + 8;
    const float scl = 0.08838834764831845f;

    for (int c = 0; c < nch; c++) {
        CP_WAIT(2);
        __syncthreads();
        if (c + 3 < nch) ISSUE_CHUNK(c + 3);

        const int jt = c >> 3, ty = (c >> 2) & 1, kt = c & 3;
        const uint32_t sBb = sb + FSM_R + (c & 3) * 16384;

        if (ty == 0) {
            if (kt == 0) {
#pragma unroll
                for (int n = 0; n < 16; n++)
#pragma unroll
                    for (int q = 0; q < 4; q++) S[n][q] = 0.f;
            }
            const uint32_t sAq = sb + FSM_Q + kt * 16384;
#pragma unroll
            for (int ks = 0; ks < 4; ks++) {
                uint32_t af[4];
                LDSM_X4(af, sAq + rowAf + unitA[ks]);
                uint32_t bfr[8][4];
#pragma unroll
                for (int p = 0; p < 8; p++) LDSM_X4(bfr[p], sBb + rowB[p] + unitB[ks]);
#pragma unroll
                for (int n = 0; n < 16; n++)
                    MMA_TF32(S[n], af, &bfr[n >> 1][(n & 1) * 2]);
            }

            if (kt == 3) {
#pragma unroll
                for (int n = 0; n < 16; n++)
#pragma unroll
                    for (int q = 0; q < 4; q++) S[n][q] *= scl;

                if (jt == itile) {
#pragma unroll
                    for (int n = 0; n < 16; n++) {
                        const int c0 = n * 8 + 2 * tg;
                        if (c0 > rl0)     S[n][0] = -1e30f;
                        if (c0 + 1 > rl0) S[n][1] = -1e30f;
                        if (c0 > rl1)     S[n][2] = -1e30f;
                        if (c0 + 1 > rl1) S[n][3] = -1e30f;
                    }
                }

                float tm0 = -1e30f, tm1 = -1e30f;
#pragma unroll
                for (int n = 0; n < 16; n++) {
                    tm0 = fmaxf(tm0, fmaxf(S[n][0], S[n][1]));
                    tm1 = fmaxf(tm1, fmaxf(S[n][2], S[n][3]));
                }
                tm0 = fmaxf(tm0, __shfl_xor_sync(0xFFFFFFFF, tm0, 1));
                tm0 = fmaxf(tm0, __shfl_xor_sync(0xFFFFFFFF, tm0, 2));
                tm1 = fmaxf(tm1, __shfl_xor_sync(0xFFFFFFFF, tm1, 1));
                tm1 = fmaxf(tm1, __shfl_xor_sync(0xFFFFFFFF, tm1, 2));

                const float mn0 = fmaxf(mrow0, tm0);
                const float mn1 = fmaxf(mrow1, tm1);
                const float a0 = __expf(mrow0 - mn0);
                const float a1 = __expf(mrow1 - mn1);
                mrow0 = mn0; mrow1 = mn1;

                float s0 = 0.f, s1 = 0.f;
#pragma unroll
                for (int n = 0; n < 16; n++) {
                    S[n][0] = __expf(S[n][0] - mn0);
                    S[n][1] = __expf(S[n][1] - mn0);
                    S[n][2] = __expf(S[n][2] - mn1);
                    S[n][3] = __expf(S[n][3] - mn1);
                    s0 += S[n][0] + S[n][1];
                    s1 += S[n][2] + S[n][3];
                }
                s0 += __shfl_xor_sync(0xFFFFFFFF, s0, 1);
                s0 += __shfl_xor_sync(0xFFFFFFFF, s0, 2);
                s1 += __shfl_xor_sync(0xFFFFFFFF, s1, 1);
                s1 += __shfl_xor_sync(0xFFFFFFFF, s1, 2);
                lsum0 = lsum0 * a0 + s0;
                lsum1 = lsum1 * a1 + s1;

#pragma unroll
                for (int n = 0; n < 16; n++) {
                    O[n][0] *= a0; O[n][1] *= a0;
                    O[n][2] *= a1; O[n][3] *= a1;
                }

#pragma unroll
                for (int n = 0; n < 16; n++) {
                    const int cf  = n * 8 + 2 * tg;
                    const int pkt = cf >> 5;
                    const int cc  = cf & 31;
                    const uint32_t a =
                        sb + FSM_P + pkt * 16384 + rl0 * 128 +
                        ((((cc >> 2) & 7) ^ g) << 4) + (cc & 3) * 4;
                    STS64F(a, rna_tf32(S[n][0]), rna_tf32(S[n][1]));
                    STS64F(a + 8 * 128, rna_tf32(S[n][2]), rna_tf32(S[n][3]));
                }
            }
        } else {
            const uint32_t sAp = sb + FSM_P + kt * 16384;
#pragma unroll
            for (int ks = 0; ks < 4; ks++) {
                uint32_t af[4];
                LDSM_X4(af, sAp + rowAf + unitA[ks]);
                uint32_t bfr[8][4];
#pragma unroll
                for (int p = 0; p < 8; p++) LDSM_X4(bfr[p], sBb + rowB[p] + unitB[ks]);
#pragma unroll
                for (int n = 0; n < 16; n++)
                    MMA_TF32(O[n], af, &bfr[n >> 1][(n & 1) * 2]);
            }
        }
    }
#undef ISSUE_CHUNK

    const float inv0 = 1.0f / lsum0;
    const float inv1 = 1.0f / lsum1;
    const int gr0 = itile * 128 + rl0;
    const int gr1 = itile * 128 + rl1;
#pragma unroll
    for (int n = 0; n < 16; n++) {
        const int col = h * HD + n * 8 + 2 * tg;
        *(float2*)(g_attn + (size_t)gr0 * DIMC + col) =
            make_float2(rna_tf32(O[n][0] * inv0), rna_tf32(O[n][1] * inv0));
        *(float2*)(g_attn + (size_t)gr1 * DIMC + col) =
            make_float2(rna_tf32(O[n][2] * inv1), rna_tf32(O[n][3] * inv1));
    }
}

// ---------------------------------------------------------------------------
// Elementwise tf32 rounding copy (float4)
// ---------------------------------------------------------------------------
__global__ void k_round4(const float* __restrict__ src, float* __restrict__ dst, int n4)
{
    int i = blockIdx.x * blockDim.x + threadIdx.x;
    if (i >= n4) return;
    float4 v = ((const float4*)src)[i];
    v.x = rna_tf32(v.x); v.y = rna_tf32(v.y);
    v.z = rna_tf32(v.z); v.w = rna_tf32(v.w);
    ((float4*)dst)[i] = v;
}

// ---------------------------------------------------------------------------
// Tiled transpose with tf32 rounding
// ---------------------------------------------------------------------------
__global__ void k_transpose(const float* __restrict__ src, int lds,
                            float* __restrict__ dst, int ldd)
{
    __shared__ float t[32][33];
    const int c0 = blockIdx.x * 32, r0 = blockIdx.y * 32;
    for (int i = threadIdx.y; i < 32; i += 8)
        t[i][threadIdx.x] = src[(size_t)(r0 + i) * lds + c0 + threadIdx.x];
    __syncthreads();
    for (int i = threadIdx.y; i < 32; i += 8)
        dst[(size_t)(c0 + i) * ldd + r0 + threadIdx.x] = rna_tf32(t[threadIdx.x][i]);
}

// ---------------------------------------------------------------------------
// Host side
// ---------------------------------------------------------------------------
extern "C" void kernel_launch(void* const* d_in, const int* in_sizes, int n_in,
                              void* d_out, int out_size)
{
    const float* x    = (const float*)d_in[0];
    const float* Wqkv = (const float*)d_in[1];
    const float* Wo   = (const float*)d_in[2];
    float* out        = (float*)d_out;

    void *px, *pwqkvT, *pwoT, *pqkv, *pvT, *pattn;
    cudaGetSymbolAddress(&px, g_x);
    cudaGetSymbolAddress(&pwqkvT, g_wqkvT);
    cudaGetSymbolAddress(&pwoT, g_woT);
    cudaGetSymbolAddress(&pqkv, g_qkv);
    cudaGetSymbolAddress(&pvT, g_vT);
    cudaGetSymbolAddress(&pattn, g_attn);

    const int smemSz = STAGES * STAGEB;   // 128 KB
    cudaFuncSetAttribute(gemm_mma, cudaFuncAttributeMaxDynamicSharedMemorySize, smemSz);
    cudaFuncSetAttribute(flash_attn, cudaFuncAttributeMaxDynamicSharedMemorySize, FSM_TOTAL);

    // 1) tf32-round inputs; transpose+round weights
    k_round4<<<(TSEQ * DIMC / 4 + 255) / 256, 256>>>(x, (float*)px, TSEQ * DIMC / 4);
    k_transpose<<<dim3(QKVN / 32, DIMC / 32), dim3(32, 8)>>>(Wqkv, QKVN, (float*)pwqkvT, DIMC);
    k_transpose<<<dim3(DIMC / 32, DIMC / 32), dim3(32, 8)>>>(Wo, DIMC, (float*)pwoT, DIMC);

    // 2) qkv = x_r @ WqkvT^T  [2048,3072]
    gemm_mma<<<dim3(QKVN / 128, TSEQ / 128), 256, smemSz>>>(
        (const float*)px, DIMC, (const float*)pwqkvT, DIMC,
        (float*)pqkv, QKVN, DIMC, 1.0f, 1);

    // 3) V^T extraction: [2048,512] -> [512,2048]
    k_transpose<<<dim3(512 / 32, TSEQ / 32), dim3(32, 8)>>>(
        (const float*)pqkv + VOFF, QKVN, (float*)pvT, TSEQ);

    // 4) fused causal attention -> g_attn
    flash_attn<<<dim3(TSEQ / 128, NH), 256, FSM_TOTAL>>>();

    // 5) out = attn @ WoT^T
    gemm_mma<<<dim3(DIMC / 128, TSEQ / 128), 256, smemSz>>>(
        (const float*)pattn, DIMC, (const float*)pwoT, DIMC,
        out, DIMC, DIMC, 1.0f, 0);
}

// round 9
// speedup vs baseline: 6.1365x; 1.7944x over previous
#include <cuda_runtime.h>
#include <cuda_fp16.h>
#include <cstdint>
#include <math.h>

// ---------------------------------------------------------------------------
// Problem constants
// ---------------------------------------------------------------------------
#define TSEQ 2048
#define DIMC 2048
#define NH   16
#define NKV  4
#define HD   128
#define QKVN 3072
#define KOFF 2048
#define VOFF 2560

// ---------------------------------------------------------------------------
// Scratch (device globals — allocation-free per harness rules)
// ---------------------------------------------------------------------------
__device__ __half g_x[TSEQ * DIMC];
__device__ __half g_wqkvT[QKVN * DIMC];
__device__ __half g_woT[DIMC * DIMC];
__device__ __half g_qkv[TSEQ * QKVN];
__device__ __half g_vT[NKV * HD * TSEQ];
__device__ __half g_attn[TSEQ * DIMC];

// ---------------------------------------------------------------------------
// Helpers
// ---------------------------------------------------------------------------
__device__ __forceinline__ uint32_t smem_u32(const void* p) {
    uint32_t a;
    asm("{ .reg .u64 t; cvta.to.shared.u64 t, %1; cvt.u32.u64 %0, t; }" : "=r"(a) : "l"(p));
    return a;
}

#define CP_ASYNC16(dst, src) \
    asm volatile("cp.async.cg.shared.global [%0], [%1], 16;" :: "r"(dst), "l"(src) : "memory")
#define CP_COMMIT() asm volatile("cp.async.commit_group;" ::: "memory")
#define CP_WAIT(n)  asm volatile("cp.async.wait_group %0;" :: "n"(n) : "memory")

#define MMA_F16(c, a, b)                                                       \
    asm volatile(                                                              \
        "mma.sync.aligned.m16n8k16.row.col.f32.f16.f16.f32 "                   \
        "{%0,%1,%2,%3}, {%4,%5,%6,%7}, {%8,%9}, {%0,%1,%2,%3};"                \
        : "+f"((c)[0]), "+f"((c)[1]), "+f"((c)[2]), "+f"((c)[3])               \
        : "r"((a)[0]), "r"((a)[1]), "r"((a)[2]), "r"((a)[3]),                  \
          "r"((b)[0]), "r"((b)[1]))

#define LDSM_X4(r, addr)                                                       \
    asm volatile("ldmatrix.sync.aligned.m8n8.x4.shared.b16 {%0,%1,%2,%3}, [%4];" \
        : "=r"((r)[0]), "=r"((r)[1]), "=r"((r)[2]), "=r"((r)[3]) : "r"(addr))

#define STSU32(addr, v) \
    asm volatile("st.shared.u32 [%0], %1;" :: "r"(addr), "r"(v) : "memory")

__device__ __forceinline__ uint32_t pack_h2(float a, float b) {
    __half2 h = __floats2half2_rn(a, b);
    return *(uint32_t*)&h;
}

// ---------------------------------------------------------------------------
// Dense fp16 tile GEMM: C[128,128] = A[128,K] @ B[128,K]^T, fp32 accum.
// 256 threads, 8 warps (4M x 2N), warp tile 32x64, 4-stage cp.async ring.
// A stage row = 128B = 64 fp16 = 4 k16-slices. Fragments via ldmatrix.x4.
// ---------------------------------------------------------------------------
#define STAGES 4
#define ABYTES (128 * 128)      // 128 rows x 128B
#define STAGEB (2 * ABYTES)

__global__ void __launch_bounds__(256, 1) gemm_h(
    const __half* __restrict__ A, int lda,
    const __half* __restrict__ B, int ldb,
    void* __restrict__ Cv, int ldc,
    int K, int outHalf)
{
    extern __shared__ char smem[];
    const uint32_t smemBase = smem_u32(smem);

    const int bx = blockIdx.x, by = blockIdx.y;
    const int m0 = by * 128;
    const int n0 = bx * 128;
    const int tid = threadIdx.x;
    const int wid = tid >> 5, lane = tid & 31;
    const int g = lane >> 2, tg = lane & 3;
    const int wm = (wid & 3) * 32;
    const int wn = (wid >> 2) * 64;
    const int nkt = K >> 6;   // 64 fp16 per stage

    // cp.async loader: 1024 16B units per operand, 4 per thread
    int lrow[4], lu8[4];
    uint32_t lsw[4];
#pragma unroll
    for (int i = 0; i < 4; i++) {
        int id = tid + i * 256;
        lrow[i] = id >> 3;
        lu8[i]  = (id & 7) * 8;     // halves
        lsw[i]  = (uint32_t)(lrow[i] * 128 + (((id & 7) ^ (lrow[i] & 7)) << 4));
    }

#define ISSUE_STAGE(kt)                                                        \
    do {                                                                       \
        const uint32_t sA = smemBase + ((kt) & (STAGES - 1)) * STAGEB;         \
        const uint32_t sB = sA + ABYTES;                                       \
        _Pragma("unroll")                                                      \
        for (int i = 0; i < 4; i++) {                                          \
            CP_ASYNC16(sA + lsw[i],                                            \
                       A + (size_t)(m0 + lrow[i]) * lda + (kt) * 64 + lu8[i]); \
            CP_ASYNC16(sB + lsw[i],                                            \
                       B + (size_t)(n0 + lrow[i]) * ldb + (kt) * 64 + lu8[i]); \
        }                                                                      \
        CP_COMMIT();                                                           \
    } while (0)

    const int r7 = lane & 7;
    const int b3 = (lane >> 3) & 1;
    const int b4 = (lane >> 4) & 1;
    uint32_t rowA[2], rowB[4], unitA[4], unitB[4];
#pragma unroll
    for (int m = 0; m < 2; m++) rowA[m] = (uint32_t)((wm + m * 16 + b3 * 8 + r7) * 128);
#pragma unroll
    for (int p = 0; p < 4; p++) rowB[p] = (uint32_t)((wn + (2 * p + b4) * 8 + r7) * 128);
#pragma unroll
    for (int ks = 0; ks < 4; ks++) {
        unitA[ks] = (uint32_t)(((2 * ks + b4) ^ r7) << 4);
        unitB[ks] = (uint32_t)(((2 * ks + b3) ^ r7) << 4);
    }

    float acc[2][8][4];
#pragma unroll
    for (int m = 0; m < 2; m++)
#pragma unroll
        for (int n = 0; n < 8; n++)
#pragma unroll
            for (int q = 0; q < 4; q++) acc[m][n][q] = 0.f;

    for (int s = 0; s < STAGES - 1 && s < nkt; s++) ISSUE_STAGE(s);

    for (int kt = 0; kt < nkt; kt++) {
        CP_WAIT(STAGES - 2);
        __syncthreads();
        if (kt + STAGES - 1 < nkt) ISSUE_STAGE(kt + STAGES - 1);

        const uint32_t sA = smemBase + (kt & (STAGES - 1)) * STAGEB;
        const uint32_t sB = sA + ABYTES;

#pragma unroll
        for (int ks = 0; ks < 4; ks++) {
            uint32_t af[2][4];
            LDSM_X4(af[0], sA + rowA[0] + unitA[ks]);
            LDSM_X4(af[1], sA + rowA[1] + unitA[ks]);
            uint32_t bfr[4][4];
#pragma unroll
            for (int p = 0; p < 4; p++) LDSM_X4(bfr[p], sB + rowB[p] + unitB[ks]);
#pragma unroll
            for (int m = 0; m < 2; m++)
#pragma unroll
                for (int n = 0; n < 8; n++)
                    MMA_F16(acc[m][n], af[m], &bfr[n >> 1][(n & 1) * 2]);
        }
    }

#pragma unroll
    for (int m = 0; m < 2; m++) {
        const int r0 = m0 + wm + m * 16 + g;
#pragma unroll
        for (int n = 0; n < 8; n++) {
            const int col = n0 + wn + n * 8 + 2 * tg;
            if (outHalf) {
                __half* C = (__half*)Cv;
                *(uint32_t*)(C + (size_t)r0 * ldc + col) =
                    pack_h2(acc[m][n][0], acc[m][n][1]);
                *(uint32_t*)(C + (size_t)(r0 + 8) * ldc + col) =
                    pack_h2(acc[m][n][2], acc[m][n][3]);
            } else {
                float* C = (float*)Cv;
                *(float2*)(C + (size_t)r0 * ldc + col) =
                    make_float2(acc[m][n][0], acc[m][n][1]);
                *(float2*)(C + (size_t)(r0 + 8) * ldc + col) =
                    make_float2(acc[m][n][2], acc[m][n][3]);
            }
        }
    }
#undef ISSUE_STAGE
}

// ---------------------------------------------------------------------------
// Fused causal flash attention (fp16 mma, fp32 accum).
// One CTA per (q-row-tile, head). 8 warps x 16 q rows.
// smem: Qs 32KB (2 chunks) | Ps 32KB (2 chunks) | ring 4x16KB = 128KB total.
// Per j-tile: K0,K1 (S mma) -> softmax -> V0,V1 (PV mma). depth-3 prefetch.
// ---------------------------------------------------------------------------
#define FSM_Q 0
#define FSM_P 32768
#define FSM_R 65536
#define FSM_TOTAL (128 * 1024)

__global__ void __launch_bounds__(256, 1) flash_attn()
{
    extern __shared__ char smem[];
    const uint32_t sb = smem_u32(smem);

    const int h     = blockIdx.y;
    const int itile = (int)gridDim.x - 1 - (int)blockIdx.x;
    const int kvh   = h >> 2;
    const int tid   = threadIdx.x;
    const int lane  = tid & 31;
    const int wid   = tid >> 5;
    const int g     = lane >> 2, tg = lane & 3;
    const int wr    = wid * 16;

    int lrow[4], lu8[4];
    uint32_t lsw[4];
#pragma unroll
    for (int i = 0; i < 4; i++) {
        int id = tid + i * 256;
        lrow[i] = id >> 3;
        lu8[i]  = (id & 7) * 8;
        lsw[i]  = (uint32_t)(lrow[i] * 128 + (((id & 7) ^ (lrow[i] & 7)) << 4));
    }

    const __half* Qg = g_qkv + (size_t)(itile * 128) * QKVN + h * HD;
    const __half* Kg = g_qkv + KOFF + (size_t)kvh * HD;
    const __half* Vg = g_vT + (size_t)(kvh * HD) * TSEQ;

    // Q tile: 2 chunks (d halves)
#pragma unroll
    for (int kt = 0; kt < 2; kt++)
#pragma unroll
        for (int i = 0; i < 4; i++)
            CP_ASYNC16(sb + FSM_Q + kt * 16384 + lsw[i],
                       Qg + (size_t)lrow[i] * QKVN + kt * 64 + lu8[i]);
    CP_COMMIT();

    const int nch = 4 * (itile + 1);

#define ISSUE_CHUNK(c)                                                         \
    do {                                                                       \
        const int _jt = (c) >> 2, _ty = ((c) >> 1) & 1, _kt = (c) & 1;         \
        const uint32_t _dst = sb + FSM_R + ((c) & 3) * 16384;                  \
        if (_ty == 0) {                                                        \
            _Pragma("unroll")                                                  \
            for (int i = 0; i < 4; i++)                                        \
                CP_ASYNC16(_dst + lsw[i],                                      \
                           Kg + (size_t)(_jt * 128 + lrow[i]) * QKVN + _kt * 64 + lu8[i]); \
        } else {                                                               \
            _Pragma("unroll")                                                  \
            for (int i = 0; i < 4; i++)                                        \
                CP_ASYNC16(_dst + lsw[i],                                      \
                           Vg + (size_t)lrow[i] * TSEQ + _jt * 128 + _kt * 64 + lu8[i]); \
        }                                                                      \
        CP_COMMIT();                                                           \
    } while (0)

    for (int c = 0; c < 3; c++) ISSUE_CHUNK(c);

    const int r7 = lane & 7;
    const int b3 = (lane >> 3) & 1;
    const int b4 = (lane >> 4) & 1;
    const uint32_t rowAf = (uint32_t)((wr + b3 * 8 + r7) * 128);
    uint32_t rowB[8], unitA[4], unitB[4];
#pragma unroll
    for (int p = 0; p < 8; p++) rowB[p] = (uint32_t)(((2 * p + b4) * 8 + r7) * 128);
#pragma unroll
    for (int ks = 0; ks < 4; ks++) {
        unitA[ks] = (uint32_t)(((2 * ks + b4) ^ r7) << 4);
        unitB[ks] = (uint32_t)(((2 * ks + b3) ^ r7) << 4);
    }

    float S[16][4], O[16][4];
#pragma unroll
    for (int n = 0; n < 16; n++)
#pragma unroll
        for (int q = 0; q < 4; q++) O[n][q] = 0.f;
    float mrow0 = -1e30f, mrow1 = -1e30f;
    float lsum0 = 0.f, lsum1 = 0.f;

    const int rl0 = wr + g;
    const int rl1 = wr + g + 8;
    const float scl = 0.08838834764831845f;

    for (int c = 0; c < nch; c++) {
        CP_WAIT(2);
        __syncthreads();
        if (c + 3 < nch) ISSUE_CHUNK(c + 3);

        const int jt = c >> 2, ty = (c >> 1) & 1, kt = c & 1;
        const uint32_t sBb = sb + FSM_R + (c & 3) * 16384;

        if (ty == 0) {
            if (kt == 0) {
#pragma unroll
                for (int n = 0; n < 16; n++)
#pragma unroll
                    for (int q = 0; q < 4; q++) S[n][q] = 0.f;
            }
            const uint32_t sAq = sb + FSM_Q + kt * 16384;
#pragma unroll
            for (int ks = 0; ks < 4; ks++) {
                uint32_t af[4];
                LDSM_X4(af, sAq + rowAf + unitA[ks]);
                uint32_t bfr[8][4];
#pragma unroll
                for (int p = 0; p < 8; p++) LDSM_X4(bfr[p], sBb + rowB[p] + unitB[ks]);
#pragma unroll
                for (int n = 0; n < 16; n++)
                    MMA_F16(S[n], af, &bfr[n >> 1][(n & 1) * 2]);
            }

            if (kt == 1) {
                // ---- online softmax ----
#pragma unroll
                for (int n = 0; n < 16; n++)
#pragma unroll
                    for (int q = 0; q < 4; q++) S[n][q] *= scl;

                if (jt == itile) {
#pragma unroll
                    for (int n = 0; n < 16; n++) {
                        const int c0 = n * 8 + 2 * tg;
                        if (c0 > rl0)     S[n][0] = -1e30f;
                        if (c0 + 1 > rl0) S[n][1] = -1e30f;
                        if (c0 > rl1)     S[n][2] = -1e30f;
                        if (c0 + 1 > rl1) S[n][3] = -1e30f;
                    }
                }

                float tm0 = -1e30f, tm1 = -1e30f;
#pragma unroll
                for (int n = 0; n < 16; n++) {
                    tm0 = fmaxf(tm0, fmaxf(S[n][0], S[n][1]));
                    tm1 = fmaxf(tm1, fmaxf(S[n][2], S[n][3]));
                }
                tm0 = fmaxf(tm0, __shfl_xor_sync(0xFFFFFFFF, tm0, 1));
                tm0 = fmaxf(tm0, __shfl_xor_sync(0xFFFFFFFF, tm0, 2));
                tm1 = fmaxf(tm1, __shfl_xor_sync(0xFFFFFFFF, tm1, 1));
                tm1 = fmaxf(tm1, __shfl_xor_sync(0xFFFFFFFF, tm1, 2));

                const float mn0 = fmaxf(mrow0, tm0);
                const float mn1 = fmaxf(mrow1, tm1);
                const float a0 = __expf(mrow0 - mn0);
                const float a1 = __expf(mrow1 - mn1);
                mrow0 = mn0; mrow1 = mn1;

                float s0 = 0.f, s1 = 0.f;
#pragma unroll
                for (int n = 0; n < 16; n++) {
                    S[n][0] = __expf(S[n][0] - mn0);
                    S[n][1] = __expf(S[n][1] - mn0);
                    S[n][2] = __expf(S[n][2] - mn1);
                    S[n][3] = __expf(S[n][3] - mn1);
                    s0 += S[n][0] + S[n][1];
                    s1 += S[n][2] + S[n][3];
                }
                s0 += __shfl_xor_sync(0xFFFFFFFF, s0, 1);
                s0 += __shfl_xor_sync(0xFFFFFFFF, s0, 2);
                s1 += __shfl_xor_sync(0xFFFFFFFF, s1, 1);
                s1 += __shfl_xor_sync(0xFFFFFFFF, s1, 2);
                lsum0 = lsum0 * a0 + s0;
                lsum1 = lsum1 * a1 + s1;

#pragma unroll
                for (int n = 0; n < 16; n++) {
                    O[n][0] *= a0; O[n][1] *= a0;
                    O[n][2] *= a1; O[n][3] *= a1;
                }

                // write P (fp16) into Ps chunks; own-warp rows only
#pragma unroll
                for (int n = 0; n < 16; n++) {
                    const uint32_t a =
                        sb + FSM_P + ((n >> 3) * 16384) + rl0 * 128 +
                        (((n & 7) ^ (rl0 & 7)) << 4) + tg * 4;
                    STSU32(a, pack_h2(S[n][0], S[n][1]));
                    STSU32(a + 1024, pack_h2(S[n][2], S[n][3]));
                }
            }
        } else {
            // ---- PV: A = P chunk kt (j-half), B = V^T chunk ----
            const uint32_t sAp = sb + FSM_P + kt * 16384;
#pragma unroll
            for (int ks = 0; ks < 4; ks++) {
                uint32_t af[4];
                LDSM_X4(af, sAp + rowAf + unitA[ks]);
                uint32_t bfr[8][4];
#pragma unroll
                for (int p = 0; p < 8; p++) LDSM_X4(bfr[p], sBb + rowB[p] + unitB[ks]);
#pragma unroll
                for (int n = 0; n < 16; n++)
                    MMA_F16(O[n], af, &bfr[n >> 1][(n & 1) * 2]);
            }
        }
    }
#undef ISSUE_CHUNK

    // epilogue: normalize, store fp16 to g_attn
    const float inv0 = 1.0f / lsum0;
    const float inv1 = 1.0f / lsum1;
    const int gr0 = itile * 128 + rl0;
    const int gr1 = itile * 128 + rl1;
#pragma unroll
    for (int n = 0; n < 16; n++) {
        const int col = h * HD + n * 8 + 2 * tg;
        *(uint32_t*)(g_attn + (size_t)gr0 * DIMC + col) =
            pack_h2(O[n][0] * inv0, O[n][1] * inv0);
        *(uint32_t*)(g_attn + (size_t)gr1 * DIMC + col) =
            pack_h2(O[n][2] * inv1, O[n][3] * inv1);
    }
}

// ---------------------------------------------------------------------------
// fp32 -> fp16 elementwise convert (4 per thread)
// ---------------------------------------------------------------------------
__global__ void k_cvt_h(const float* __restrict__ src, __half* __restrict__ dst, int n4)
{
    int i = blockIdx.x * blockDim.x + threadIdx.x;
    if (i >= n4) return;
    float4 v = ((const float4*)src)[i];
    uint2 o;
    o.x = pack_h2(v.x, v.y);
    o.y = pack_h2(v.z, v.w);
    ((uint2*)dst)[i] = o;
}

// ---------------------------------------------------------------------------
// Transpose fp32 -> fp16: dst[c][r] = (half)src[r][c]
// ---------------------------------------------------------------------------
__global__ void k_transpose_fh(const float* __restrict__ src, int lds,
                               __half* __restrict__ dst, int ldd)
{
    __shared__ float t[32][33];
    const int c0 = blockIdx.x * 32, r0 = blockIdx.y * 32;
    for (int i = threadIdx.y; i < 32; i += 8)
        t[i][threadIdx.x] = src[(size_t)(r0 + i) * lds + c0 + threadIdx.x];
    __syncthreads();
    for (int i = threadIdx.y; i < 32; i += 8)
        dst[(size_t)(c0 + i) * ldd + r0 + threadIdx.x] = __float2half_rn(t[threadIdx.x][i]);
}

// ---------------------------------------------------------------------------
// Transpose fp16 -> fp16 (V^T extraction)
// ---------------------------------------------------------------------------
__global__ void k_transpose_hh(const __half* __restrict__ src, int lds,
                               __half* __restrict__ dst, int ldd)
{
    __shared__ __half t[32][34];
    const int c0 = blockIdx.x * 32, r0 = blockIdx.y * 32;
    for (int i = threadIdx.y; i < 32; i += 8)
        t[i][threadIdx.x] = src[(size_t)(r0 + i) * lds + c0 + threadIdx.x];
    __syncthreads();
    for (int i = threadIdx.y; i < 32; i += 8)
        dst[(size_t)(c0 + i) * ldd + r0 + threadIdx.x] = t[threadIdx.x][i];
}

// ---------------------------------------------------------------------------
// Host side
// ---------------------------------------------------------------------------
extern "C" void kernel_launch(void* const* d_in, const int* in_sizes, int n_in,
                              void* d_out, int out_size)
{
    const float* x    = (const float*)d_in[0];
    const float* Wqkv = (const float*)d_in[1];
    const float* Wo   = (const float*)d_in[2];

    void *px, *pwqkvT, *pwoT, *pqkv, *pvT, *pattn;
    cudaGetSymbolAddress(&px, g_x);
    cudaGetSymbolAddress(&pwqkvT, g_wqkvT);
    cudaGetSymbolAddress(&pwoT, g_woT);
    cudaGetSymbolAddress(&pqkv, g_qkv);
    cudaGetSymbolAddress(&pvT, g_vT);
    cudaGetSymbolAddress(&pattn, g_attn);

    const int smemSz = STAGES * STAGEB;   // 128 KB
    cudaFuncSetAttribute(gemm_h, cudaFuncAttributeMaxDynamicSharedMemorySize, smemSz);
    cudaFuncSetAttribute(flash_attn, cudaFuncAttributeMaxDynamicSharedMemorySize, FSM_TOTAL);

    // 1) fp16-convert x; transpose+convert weights
    k_cvt_h<<<(TSEQ * DIMC / 4 + 255) / 256, 256>>>(x, (__half*)px, TSEQ * DIMC / 4);
    k_transpose_fh<<<dim3(QKVN / 32, DIMC / 32), dim3(32, 8)>>>(Wqkv, QKVN, (__half*)pwqkvT, DIMC);
    k_transpose_fh<<<dim3(DIMC / 32, DIMC / 32), dim3(32, 8)>>>(Wo, DIMC, (__half*)pwoT, DIMC);

    // 2) qkv = x_h @ WqkvT^T  [2048,3072] (fp16 out)
    gemm_h<<<dim3(QKVN / 128, TSEQ / 128), 256, smemSz>>>(
        (const __half*)px, DIMC, (const __half*)pwqkvT, DIMC,
        pqkv, QKVN, DIMC, 1);

    // 3) V^T extraction: [2048,512] -> [512,2048] fp16
    k_transpose_hh<<<dim3(512 / 32, TSEQ / 32), dim3(32, 8)>>>(
        (const __half*)pqkv + VOFF, QKVN, (__half*)pvT, TSEQ);

    // 4) fused causal attention -> g_attn (fp16)
    flash_attn<<<dim3(TSEQ / 128, NH), 256, FSM_TOTAL>>>();

    // 5) out = attn @ WoT^T (fp32 out)
    gemm_h<<<dim3(DIMC / 128, TSEQ / 128), 256, smemSz>>>(
        (const __half*)pattn, DIMC, (const __half*)pwoT, DIMC,
        d_out, DIMC, DIMC, 0);
}

// round 11
// speedup vs baseline: 6.6058x; 1.0765x over previous
#include <cuda_runtime.h>
#include <cuda_fp16.h>
#include <cstdint>
#include <math.h>

// ---------------------------------------------------------------------------
// Problem constants
// ---------------------------------------------------------------------------
#define TSEQ 2048
#define DIMC 2048
#define NH   16
#define NKV  4
#define HD   128
#define QKVN 3072
#define KOFF 2048
#define VOFF 2560

// ---------------------------------------------------------------------------
// Scratch (device globals — allocation-free per harness rules)
// ---------------------------------------------------------------------------
__device__ __half g_x[TSEQ * DIMC];       // fp16 x
__device__ __half g_wqkv[DIMC * QKVN];    // fp16 W_qkv (natural [K,N])
__device__ __half g_wo[DIMC * DIMC];      // fp16 W_o   (natural [K,N])
__device__ __half g_qkv[TSEQ * QKVN];     // qkv (fp16)
__device__ __half g_attn[TSEQ * DIMC];    // attn out (fp16)

// ---------------------------------------------------------------------------
// Helpers
// ---------------------------------------------------------------------------
__device__ __forceinline__ uint32_t smem_u32(const void* p) {
    uint32_t a;
    asm("{ .reg .u64 t; cvta.to.shared.u64 t, %1; cvt.u32.u64 %0, t; }" : "=r"(a) : "l"(p));
    return a;
}

#define CP_ASYNC16(dst, src) \
    asm volatile("cp.async.cg.shared.global [%0], [%1], 16;" :: "r"(dst), "l"(src) : "memory")
#define CP_COMMIT() asm volatile("cp.async.commit_group;" ::: "memory")
#define CP_WAIT(n)  asm volatile("cp.async.wait_group %0;" :: "n"(n) : "memory")

#define MMA_F16(c, a, b)                                                       \
    asm volatile(                                                              \
        "mma.sync.aligned.m16n8k16.row.col.f32.f16.f16.f32 "                   \
        "{%0,%1,%2,%3}, {%4,%5,%6,%7}, {%8,%9}, {%0,%1,%2,%3};"                \
        : "+f"((c)[0]), "+f"((c)[1]), "+f"((c)[2]), "+f"((c)[3])               \
        : "r"((a)[0]), "r"((a)[1]), "r"((a)[2]), "r"((a)[3]),                  \
          "r"((b)[0]), "r"((b)[1]))

#define LDSM_X4(r, addr)                                                       \
    asm volatile("ldmatrix.sync.aligned.m8n8.x4.shared.b16 {%0,%1,%2,%3}, [%4];" \
        : "=r"((r)[0]), "=r"((r)[1]), "=r"((r)[2]), "=r"((r)[3]) : "r"(addr))

#define LDSM_X4_T(r, addr)                                                     \
    asm volatile("ldmatrix.sync.aligned.m8n8.x4.trans.shared.b16 {%0,%1,%2,%3}, [%4];" \
        : "=r"((r)[0]), "=r"((r)[1]), "=r"((r)[2]), "=r"((r)[3]) : "r"(addr))

#define STSU32(addr, v) \
    asm volatile("st.shared.u32 [%0], %1;" :: "r"(addr), "r"(v) : "memory")

__device__ __forceinline__ uint32_t pack_h2(float a, float b) {
    __half2 h = __floats2half2_rn(a, b);
    return *(uint32_t*)&h;
}

// ---------------------------------------------------------------------------
// Dense fp16 GEMM: C[128,128] tile = A[128,K] @ B[K,N] (B natural row-major).
// A: k-major rows (128 x 128B, XOR swizzle, normal ldmatrix).
// B: 64 k-rows x 256B (128 n fp16), per-128B swizzle, trans ldmatrix.
// 256 threads, 8 warps (4M x 2N), warp tile 32x64, 4-stage cp.async ring.
// ---------------------------------------------------------------------------
#define STAGES 4
#define ABYTES (128 * 128)      // A: 128 rows x 128B = 16KB
#define BBYTES (64 * 256)       // B: 64 rows x 256B = 16KB
#define STAGEB (ABYTES + BBYTES)

__global__ void __launch_bounds__(256, 1) gemm_h(
    const __half* __restrict__ A, int lda,
    const __half* __restrict__ B, int ldb,
    void* __restrict__ Cv, int ldc,
    int K, int outHalf)
{
    extern __shared__ char smem[];
    const uint32_t smemBase = smem_u32(smem);

    const int bx = blockIdx.x, by = blockIdx.y;
    const int m0 = by * 128;
    const int n0 = bx * 128;
    const int tid = threadIdx.x;
    const int wid = tid >> 5, lane = tid & 31;
    const int g = lane >> 2, tg = lane & 3;
    const int wm = (wid & 3) * 32;
    const int wn = (wid >> 2) * 64;
    const int nkt = K >> 6;   // 64 k per stage

    // A loader: 1024 16B units (128 rows x 8 units), 4 per thread
    int larow[4], lau8[4];
    uint32_t lasw[4];
    // B loader: 1024 16B units (64 rows x 16 units), 4 per thread
    int lbrow[4], lbu8[4];
    uint32_t lbsw[4];
#pragma unroll
    for (int i = 0; i < 4; i++) {
        int id = tid + i * 256;
        larow[i] = id >> 3;
        lau8[i]  = (id & 7) * 8;
        lasw[i]  = (uint32_t)(larow[i] * 128 + (((id & 7) ^ (larow[i] & 7)) << 4));
        lbrow[i] = id >> 4;
        int bu   = id & 15;
        lbu8[i]  = bu * 8;
        lbsw[i]  = (uint32_t)(lbrow[i] * 256 + (((bu & 8) | ((bu & 7) ^ (lbrow[i] & 7))) << 4));
    }

#define ISSUE_STAGE(kt)                                                        \
    do {                                                                       \
        const uint32_t sA = smemBase + ((kt) & (STAGES - 1)) * STAGEB;         \
        const uint32_t sB = sA + ABYTES;                                       \
        _Pragma("unroll")                                                      \
        for (int i = 0; i < 4; i++) {                                          \
            CP_ASYNC16(sA + lasw[i],                                           \
                       A + (size_t)(m0 + larow[i]) * lda + (kt) * 64 + lau8[i]); \
            CP_ASYNC16(sB + lbsw[i],                                           \
                       B + (size_t)((kt) * 64 + lbrow[i]) * ldb + n0 + lbu8[i]); \
        }                                                                      \
        CP_COMMIT();                                                           \
    } while (0)

    // A fragment addresses (normal ldmatrix)
    const int r7 = lane & 7;
    const int b3 = (lane >> 3) & 1;
    const int b4 = (lane >> 4) & 1;
    uint32_t rowA[2], unitA[4];
#pragma unroll
    for (int m = 0; m < 2; m++) rowA[m] = (uint32_t)((wm + m * 16 + b3 * 8 + r7) * 128);
#pragma unroll
    for (int ks = 0; ks < 4; ks++) unitA[ks] = (uint32_t)(((2 * ks + b4) ^ r7) << 4);

    // B fragment addresses (trans ldmatrix): matrix mi = lane>>3
    const int mi = lane >> 3;
    const int kb = (mi & 1) * 8 + r7;     // k-row within k16
    uint32_t btoff[4];
#pragma unroll
    for (int p = 0; p < 4; p++) {
        int u = ((wn + p * 16 + (mi >> 1) * 8) >> 3);  // 16B unit within 256B row
        btoff[p] = (uint32_t)(kb * 256 + (((u & 8) | ((u & 7) ^ r7)) << 4));
    }

    float acc[2][8][4];
#pragma unroll
    for (int m = 0; m < 2; m++)
#pragma unroll
        for (int n = 0; n < 8; n++)
#pragma unroll
            for (int q = 0; q < 4; q++) acc[m][n][q] = 0.f;

    for (int s = 0; s < STAGES - 1 && s < nkt; s++) ISSUE_STAGE(s);

    for (int kt = 0; kt < nkt; kt++) {
        CP_WAIT(STAGES - 2);
        __syncthreads();
        if (kt + STAGES - 1 < nkt) ISSUE_STAGE(kt + STAGES - 1);

        const uint32_t sA = smemBase + (kt & (STAGES - 1)) * STAGEB;
        const uint32_t sB = sA + ABYTES;

#pragma unroll
        for (int ks = 0; ks < 4; ks++) {
            uint32_t af[2][4];
            LDSM_X4(af[0], sA + rowA[0] + unitA[ks]);
            LDSM_X4(af[1], sA + rowA[1] + unitA[ks]);
            uint32_t bfr[4][4];
#pragma unroll
            for (int p = 0; p < 4; p++)
                LDSM_X4_T(bfr[p], sB + ks * 4096 + btoff[p]);
#pragma unroll
            for (int m = 0; m < 2; m++)
#pragma unroll
                for (int n = 0; n < 8; n++)
                    MMA_F16(acc[m][n], af[m], &bfr[n >> 1][(n & 1) * 2]);
        }
    }

#pragma unroll
    for (int m = 0; m < 2; m++) {
        const int r0 = m0 + wm + m * 16 + g;
#pragma unroll
        for (int n = 0; n < 8; n++) {
            const int col = n0 + wn + n * 8 + 2 * tg;
            if (outHalf) {
                __half* C = (__half*)Cv;
                *(uint32_t*)(C + (size_t)r0 * ldc + col) =
                    pack_h2(acc[m][n][0], acc[m][n][1]);
                *(uint32_t*)(C + (size_t)(r0 + 8) * ldc + col) =
                    pack_h2(acc[m][n][2], acc[m][n][3]);
            } else {
                float* C = (float*)Cv;
                *(float2*)(C + (size_t)r0 * ldc + col) =
                    make_float2(acc[m][n][0], acc[m][n][1]);
                *(float2*)(C + (size_t)(r0 + 8) * ldc + col) =
                    make_float2(acc[m][n][2], acc[m][n][3]);
            }
        }
    }
#undef ISSUE_STAGE
}

// ---------------------------------------------------------------------------
// Fused causal flash attention (fp16 mma, fp32 accum).
// One CTA per (q-row-tile, head). 8 warps x 16 q rows.
// smem: Qs 32KB | Ps 32KB | ring 4x16KB = 128KB.
// K chunks: 128 tokens x 64 d (k-major, normal ldmatrix).
// V chunks: 64 j-rows x 128 d direct from g_qkv (trans ldmatrix).
// ---------------------------------------------------------------------------
#define FSM_Q 0
#define FSM_P 32768
#define FSM_R 65536
#define FSM_TOTAL (128 * 1024)

__global__ void __launch_bounds__(256, 1) flash_attn()
{
    extern __shared__ char smem[];
    const uint32_t sb = smem_u32(smem);

    const int h     = blockIdx.y;
    const int itile = (int)gridDim.x - 1 - (int)blockIdx.x;
    const int kvh   = h >> 2;
    const int tid   = threadIdx.x;
    const int lane  = tid & 31;
    const int wid   = tid >> 5;
    const int g     = lane >> 2, tg = lane & 3;
    const int wr    = wid * 16;

    // loaders: 128x8-unit (Q/K) and 64x16-unit (V)
    int lrow[4], lu8[4], vrow[4], vu8[4];
    uint32_t lsw[4], vsw[4];
#pragma unroll
    for (int i = 0; i < 4; i++) {
        int id = tid + i * 256;
        lrow[i] = id >> 3;
        lu8[i]  = (id & 7) * 8;
        lsw[i]  = (uint32_t)(lrow[i] * 128 + (((id & 7) ^ (lrow[i] & 7)) << 4));
        vrow[i] = id >> 4;
        int vu  = id & 15;
        vu8[i]  = vu * 8;
        vsw[i]  = (uint32_t)(vrow[i] * 256 + (((vu & 8) | ((vu & 7) ^ (vrow[i] & 7))) << 4));
    }

    const __half* Qg = g_qkv + (size_t)(itile * 128) * QKVN + h * HD;
    const __half* Kg = g_qkv + KOFF + (size_t)kvh * HD;
    const __half* Vg = g_qkv + VOFF + (size_t)kvh * HD;

    // Q tile: 2 chunks (d halves)
#pragma unroll
    for (int kt = 0; kt < 2; kt++)
#pragma unroll
        for (int i = 0; i < 4; i++)
            CP_ASYNC16(sb + FSM_Q + kt * 16384 + lsw[i],
                       Qg + (size_t)lrow[i] * QKVN + kt * 64 + lu8[i]);
    CP_COMMIT();

    const int nch = 4 * (itile + 1);

#define ISSUE_CHUNK(c)                                                         \
    do {                                                                       \
        const int _jt = (c) >> 2, _ty = ((c) >> 1) & 1, _kt = (c) & 1;         \
        const uint32_t _dst = sb + FSM_R + ((c) & 3) * 16384;                  \
        if (_ty == 0) {                                                        \
            _Pragma("unroll")                                                  \
            for (int i = 0; i < 4; i++)                                        \
                CP_ASYNC16(_dst + lsw[i],                                      \
                           Kg + (size_t)(_jt * 128 + lrow[i]) * QKVN + _kt * 64 + lu8[i]); \
        } else {                                                               \
            _Pragma("unroll")                                                  \
            for (int i = 0; i < 4; i++)                                        \
                CP_ASYNC16(_dst + vsw[i],                                      \
                           Vg + (size_t)(_jt * 128 + _kt * 64 + vrow[i]) * QKVN + vu8[i]); \
        }                                                                      \
        CP_COMMIT();                                                           \
    } while (0)

    for (int c = 0; c < 3; c++) ISSUE_CHUNK(c);

    const int r7 = lane & 7;
    const int b3 = (lane >> 3) & 1;
    const int b4 = (lane >> 4) & 1;
    const uint32_t rowAf = (uint32_t)((wr + b3 * 8 + r7) * 128);
    uint32_t rowB[8], unitA[4], unitB[4];
#pragma unroll
    for (int p = 0; p < 8; p++) rowB[p] = (uint32_t)(((2 * p + b4) * 8 + r7) * 128);
#pragma unroll
    for (int ks = 0; ks < 4; ks++) {
        unitA[ks] = (uint32_t)(((2 * ks + b4) ^ r7) << 4);
        unitB[ks] = (uint32_t)(((2 * ks + b3) ^ r7) << 4);
    }
    // V trans-fragment offsets (d16 tiles p = 0..7)
    const int mi = lane >> 3;
    const int kb = (mi & 1) * 8 + r7;
    uint32_t vtoff[8];
#pragma unroll
    for (int p = 0; p < 8; p++) {
        int u = 2 * p + (mi >> 1);
        vtoff[p] = (uint32_t)(kb * 256 + (((u & 8) | ((u & 7) ^ r7)) << 4));
    }

    float S[16][4], O[16][4];
#pragma unroll
    for (int n = 0; n < 16; n++)
#pragma unroll
        for (int q = 0; q < 4; q++) O[n][q] = 0.f;
    float mrow0 = -1e30f, mrow1 = -1e30f;
    float lsum0 = 0.f, lsum1 = 0.f;

    const int rl0 = wr + g;
    const int rl1 = wr + g + 8;
    const float scl = 0.08838834764831845f;

    for (int c = 0; c < nch; c++) {
        CP_WAIT(2);
        __syncthreads();
        if (c + 3 < nch) ISSUE_CHUNK(c + 3);

        const int jt = c >> 2, ty = (c >> 1) & 1, kt = c & 1;
        const uint32_t sBb = sb + FSM_R + (c & 3) * 16384;

        if (ty == 0) {
            if (kt == 0) {
#pragma unroll
                for (int n = 0; n < 16; n++)
#pragma unroll
                    for (int q = 0; q < 4; q++) S[n][q] = 0.f;
            }
            const uint32_t sAq = sb + FSM_Q + kt * 16384;
#pragma unroll
            for (int ks = 0; ks < 4; ks++) {
                uint32_t af[4];
                LDSM_X4(af, sAq + rowAf + unitA[ks]);
                uint32_t bfr[8][4];
#pragma unroll
                for (int p = 0; p < 8; p++) LDSM_X4(bfr[p], sBb + rowB[p] + unitB[ks]);
#pragma unroll
                for (int n = 0; n < 16; n++)
                    MMA_F16(S[n], af, &bfr[n >> 1][(n & 1) * 2]);
            }

            if (kt == 1) {
                // ---- online softmax ----
#pragma unroll
                for (int n = 0; n < 16; n++)
#pragma unroll
                    for (int q = 0; q < 4; q++) S[n][q] *= scl;

                if (jt == itile) {
#pragma unroll
                    for (int n = 0; n < 16; n++) {
                        const int c0 = n * 8 + 2 * tg;
                        if (c0 > rl0)     S[n][0] = -1e30f;
                        if (c0 + 1 > rl0) S[n][1] = -1e30f;
                        if (c0 > rl1)     S[n][2] = -1e30f;
                        if (c0 + 1 > rl1) S[n][3] = -1e30f;
                    }
                }

                float tm0 = -1e30f, tm1 = -1e30f;
#pragma unroll
                for (int n = 0; n < 16; n++) {
                    tm0 = fmaxf(tm0, fmaxf(S[n][0], S[n][1]));
                    tm1 = fmaxf(tm1, fmaxf(S[n][2], S[n][3]));
                }
                tm0 = fmaxf(tm0, __shfl_xor_sync(0xFFFFFFFF, tm0, 1));
                tm0 = fmaxf(tm0, __shfl_xor_sync(0xFFFFFFFF, tm0, 2));
                tm1 = fmaxf(tm1, __shfl_xor_sync(0xFFFFFFFF, tm1, 1));
                tm1 = fmaxf(tm1, __shfl_xor_sync(0xFFFFFFFF, tm1, 2));

                const float mn0 = fmaxf(mrow0, tm0);
                const float mn1 = fmaxf(mrow1, tm1);
                const float a0 = __expf(mrow0 - mn0);
                const float a1 = __expf(mrow1 - mn1);
                mrow0 = mn0; mrow1 = mn1;

                float s0 = 0.f, s1 = 0.f;
#pragma unroll
                for (int n = 0; n < 16; n++) {
                    S[n][0] = __expf(S[n][0] - mn0);
                    S[n][1] = __expf(S[n][1] - mn0);
                    S[n][2] = __expf(S[n][2] - mn1);
                    S[n][3] = __expf(S[n][3] - mn1);
                    s0 += S[n][0] + S[n][1];
                    s1 += S[n][2] + S[n][3];
                }
                s0 += __shfl_xor_sync(0xFFFFFFFF, s0, 1);
                s0 += __shfl_xor_sync(0xFFFFFFFF, s0, 2);
                s1 += __shfl_xor_sync(0xFFFFFFFF, s1, 1);
                s1 += __shfl_xor_sync(0xFFFFFFFF, s1, 2);
                lsum0 = lsum0 * a0 + s0;
                lsum1 = lsum1 * a1 + s1;

#pragma unroll
                for (int n = 0; n < 16; n++) {
                    O[n][0] *= a0; O[n][1] *= a0;
                    O[n][2] *= a1; O[n][3] *= a1;
                }

                // write P (fp16) into Ps chunks; own-warp rows only
#pragma unroll
                for (int n = 0; n < 16; n++) {
                    const uint32_t a =
                        sb + FSM_P + ((n >> 3) * 16384) + rl0 * 128 +
                        (((n & 7) ^ (rl0 & 7)) << 4) + tg * 4;
                    STSU32(a, pack_h2(S[n][0], S[n][1]));
                    STSU32(a + 1024, pack_h2(S[n][2], S[n][3]));
                }
            }
        } else {
            // ---- PV: A = P chunk kt (j-half, normal), B = V chunk (trans) ----
            const uint32_t sAp = sb + FSM_P + kt * 16384;
#pragma unroll
            for (int ks = 0; ks < 4; ks++) {
                uint32_t af[4];
                LDSM_X4(af, sAp + rowAf + unitA[ks]);
                uint32_t bfr[8][4];
#pragma unroll
                for (int p = 0; p < 8; p++)
                    LDSM_X4_T(bfr[p], sBb + ks * 4096 + vtoff[p]);
#pragma unroll
                for (int n = 0; n < 16; n++)
                    MMA_F16(O[n], af, &bfr[n >> 1][(n & 1) * 2]);
            }
        }
    }
#undef ISSUE_CHUNK

    // epilogue: normalize, store fp16 to g_attn
    const float inv0 = 1.0f / lsum0;
    const float inv1 = 1.0f / lsum1;
    const int gr0 = itile * 128 + rl0;
    const int gr1 = itile * 128 + rl1;
#pragma unroll
    for (int n = 0; n < 16; n++) {
        const int col = h * HD + n * 8 + 2 * tg;
        *(uint32_t*)(g_attn + (size_t)gr0 * DIMC + col) =
            pack_h2(O[n][0] * inv0, O[n][1] * inv0);
        *(uint32_t*)(g_attn + (size_t)gr1 * DIMC + col) =
            pack_h2(O[n][2] * inv1, O[n][3] * inv1);
    }
}

// ---------------------------------------------------------------------------
// Fused fp32 -> fp16 convert for x, W_qkv, W_o (float4 granules)
// ---------------------------------------------------------------------------
#define N4_X  (TSEQ * DIMC / 4)
#define N4_W1 (DIMC * QKVN / 4)
#define N4_W2 (DIMC * DIMC / 4)

__global__ void k_cvt_all(const float* __restrict__ sx,
                          const float* __restrict__ sw1,
                          const float* __restrict__ sw2)
{
    int i = blockIdx.x * blockDim.x + threadIdx.x;
    const float* src;
    __half* dst;
    int off;
    if (i < N4_X)              { src = sx;  dst = g_x;    off = i; }
    else if (i < N4_X + N4_W1) { src = sw1; dst = g_wqkv; off = i - N4_X; }
    else if (i < N4_X + N4_W1 + N4_W2) { src = sw2; dst = g_wo; off = i - N4_X - N4_W1; }
    else return;
    float4 v = ((const float4*)src)[off];
    uint2 o;
    o.x = pack_h2(v.x, v.y);
    o.y = pack_h2(v.z, v.w);
    ((uint2*)dst)[off] = o;
}

// ---------------------------------------------------------------------------
// Host side
// ---------------------------------------------------------------------------
extern "C" void kernel_launch(void* const* d_in, const int* in_sizes, int n_in,
                              void* d_out, int out_size)
{
    const float* x    = (const float*)d_in[0];
    const float* Wqkv = (const float*)d_in[1];
    const float* Wo   = (const float*)d_in[2];

    void *px, *pwqkv, *pwo, *pqkv, *pattn;
    cudaGetSymbolAddress(&px, g_x);
    cudaGetSymbolAddress(&pwqkv, g_wqkv);
    cudaGetSymbolAddress(&pwo, g_wo);
    cudaGetSymbolAddress(&pqkv, g_qkv);
    cudaGetSymbolAddress(&pattn, g_attn);

    const int smemSz = STAGES * STAGEB;   // 128 KB
    cudaFuncSetAttribute(gemm_h, cudaFuncAttributeMaxDynamicSharedMemorySize, smemSz);
    cudaFuncSetAttribute(flash_attn, cudaFuncAttributeMaxDynamicSharedMemorySize, FSM_TOTAL);

    // 1) fused fp32 -> fp16 conversion (x, W_qkv, W_o) — no transposes
    {
        const int total = N4_X + N4_W1 + N4_W2;
        k_cvt_all<<<(total + 255) / 256, 256>>>(x, Wqkv, Wo);
    }

    // 2) qkv = x_h @ W_qkv  [2048,3072] (fp16 out; B natural [K,N])
    gemm_h<<<dim3(QKVN / 128, TSEQ / 128), 256, smemSz>>>(
        (const __half*)px, DIMC, (const __half*)pwqkv, QKVN,
        pqkv, QKVN, DIMC, 1);

    // 3) fused causal attention -> g_attn (fp16; V read in-place from g_qkv)
    flash_attn<<<dim3(TSEQ / 128, NH), 256, FSM_TOTAL>>>();

    // 4) out = attn @ W_o (fp32 out; B natural [K,N])
    gemm_h<<<dim3(DIMC / 128, TSEQ / 128), 256, smemSz>>>(
        (const __half*)pattn, DIMC, (const __half*)pwo, DIMC,
        d_out, DIMC, DIMC, 0);
}